// round 7
// baseline (speedup 1.0000x reference)
#include <cuda_runtime.h>
#include <cuda_fp16.h>
#include <math.h>
#include <stdint.h>

#define B 2
#define T 2048
#define H 16
#define DH 64
#define DIM 1024
#define M_TOTAL (B*T)      // 4096
#define SZH (B*H*T*DH)     // 4194304
#define XSZ (M_TOTAL*DIM)  // 4194304
#define WSZ (DIM*DIM)      // 1048576
#define ATT_SCALE 0.125f

// ---------------- scratch (device globals; allocation-free) ----------------
__device__ __half g_xh [XSZ];
__device__ __half g_whi[4*WSZ];
__device__ __half g_wlo[4*WSZ];
__device__ __half g_qh [SZH];
__device__ __half g_khi[SZH];
__device__ __half g_klo[SZH];
__device__ __half g_vh [SZH];
__device__ __half g_aoh[XSZ];

// ---------------- helpers ----------------
__device__ __forceinline__ uint32_t smem_u32(const void* p) {
    uint32_t a;
    asm("{ .reg .u64 t; cvta.to.shared.u64 t, %1; cvt.u32.u64 %0, t; }"
        : "=r"(a) : "l"(p));
    return a;
}

#define CP_ASYNC16(dst_u32, src_ptr) \
    asm volatile("cp.async.cg.shared.global [%0], [%1], 16;" :: "r"(dst_u32), "l"(src_ptr))
#define CP_COMMIT()  asm volatile("cp.async.commit_group;" ::: "memory")
#define CP_WAIT0()   asm volatile("cp.async.wait_group 0;" ::: "memory")
#define CP_WAIT1()   asm volatile("cp.async.wait_group 1;" ::: "memory")

#define LDM_X4(r0,r1,r2,r3, addr) \
    asm volatile("ldmatrix.sync.aligned.m8n8.x4.shared.b16 {%0,%1,%2,%3}, [%4];" \
                 : "=r"(r0), "=r"(r1), "=r"(r2), "=r"(r3) : "r"(addr))
#define LDM_X4_T(r0,r1,r2,r3, addr) \
    asm volatile("ldmatrix.sync.aligned.m8n8.x4.trans.shared.b16 {%0,%1,%2,%3}, [%4];" \
                 : "=r"(r0), "=r"(r1), "=r"(r2), "=r"(r3) : "r"(addr))

__device__ __forceinline__ void mma_f16(float* c, const uint32_t* a, const uint32_t* b) {
    asm volatile(
        "mma.sync.aligned.m16n8k16.row.col.f32.f16.f16.f32 "
        "{%0,%1,%2,%3}, {%4,%5,%6,%7}, {%8,%9}, {%0,%1,%2,%3};"
        : "+f"(c[0]), "+f"(c[1]), "+f"(c[2]), "+f"(c[3])
        : "r"(a[0]), "r"(a[1]), "r"(a[2]), "r"(a[3]), "r"(b[0]), "r"(b[1]));
}

__device__ __forceinline__ uint32_t pkh(float a, float b) {
    __half2 t = __floats2half2_rn(a, b);
    return *(uint32_t*)&t;
}
__device__ __forceinline__ void ld4h(const __half* p, float* f) {
    __half2 a = *(const __half2*)p;
    __half2 b = *(const __half2*)(p + 2);
    float2 fa = __half22float2(a), fb = __half22float2(b);
    f[0] = fa.x; f[1] = fa.y; f[2] = fb.x; f[3] = fb.y;
}

// ---------------------------------------------------------------------------
// fp32 -> fp16 (single)
// ---------------------------------------------------------------------------
__global__ void tohalf(const float* __restrict__ x, __half* __restrict__ o, int n4)
{
    int i = blockIdx.x * blockDim.x + threadIdx.x;
    if (i >= n4) return;
    float4 v = ((const float4*)x)[i];
    uint2 u;
    u.x = pkh(v.x, v.y);
    u.y = pkh(v.z, v.w);
    *(uint2*)(o + 4 * (size_t)i) = u;
}

// ---------------------------------------------------------------------------
// 4 weight matrices -> fp16 hi/lo (one launch)
// ---------------------------------------------------------------------------
__global__ void split_w4(const float* __restrict__ W0, const float* __restrict__ W1,
                         const float* __restrict__ W2, const float* __restrict__ W3,
                         __half* __restrict__ hi, __half* __restrict__ lo)
{
    int i = blockIdx.x * blockDim.x + threadIdx.x;  // over 4*WSZ/4
    int which = i >> 18;                            // WSZ/4 = 2^18
    int j = i & 0x3FFFF;
    const float* W = (which == 0) ? W0 : (which == 1) ? W1 : (which == 2) ? W2 : W3;
    float4 v = ((const float4*)W)[j];
    float f[4] = {v.x, v.y, v.z, v.w};
    float r[4];
    __half h[4];
    #pragma unroll
    for (int e = 0; e < 4; e++) {
        h[e] = __float2half_rn(f[e]);
        r[e] = f[e] - __half2float(h[e]);
    }
    size_t base = (size_t)which * WSZ + (size_t)j * 4;
    uint2 uh, ul;
    uh.x = pkh(__half2float(h[0]), __half2float(h[1]));
    uh.y = pkh(__half2float(h[2]), __half2float(h[3]));
    ul.x = pkh(r[0], r[1]);
    ul.y = pkh(r[2], r[3]);
    *(uint2*)(hi + base) = uh;
    *(uint2*)(lo + base) = ul;
}

// ---------------------------------------------------------------------------
// Tensor-core GEMM: C[m,n] = sum_k A[m,k]*W[n,k]
// A single fp16; W fp16 hi/lo (2-pass).
// mode 0: Cf fp32 row-major (N=DIM, grid.x=8)
// mode 1: QKV fused (grid.x=24): which=n0>>10 -> Q single / K hi,lo / V single,
//         scattered to (b,h,t,d) fp16.
// ---------------------------------------------------------------------------
#define BKC 32
#define RS  40
#define TILE_B (128*RS*2)          // 10240 bytes
#define STG (3*TILE_B)             // A, Wh, Wl
#define GEMM_SMEM (2*STG)          // 61440

__global__ __launch_bounds__(256) void gemm_hmma(
    const __half* __restrict__ A,
    const __half* __restrict__ Wh, const __half* __restrict__ Wl,
    float* __restrict__ Cf,
    __half* __restrict__ Cq, __half* __restrict__ Ckh,
    __half* __restrict__ Ckl, __half* __restrict__ Cv,
    int mode)
{
    extern __shared__ __align__(16) char sm[];
    const uint32_t smb = smem_u32(sm);

    const int tid  = threadIdx.x;
    const int m0   = blockIdx.y * 128;
    const int n0   = blockIdx.x * 128;
    const int wid  = tid >> 5;
    const int lane = tid & 31;
    const int g    = lane >> 2;
    const int t2   = (lane & 3) * 2;
    const int wm   = (wid & 1) * 64;
    const int wn   = (wid >> 1) * 32;

    float acc[4][4][4];
    #pragma unroll
    for (int mt = 0; mt < 4; mt++)
        #pragma unroll
        for (int nt = 0; nt < 4; nt++)
            #pragma unroll
            for (int e = 0; e < 4; e++) acc[mt][nt][e] = 0.f;

    auto load_chunk = [&](int c, int buf) {
        const int k0 = c * BKC;
        const uint32_t bb = smb + (uint32_t)buf * STG;
        #pragma unroll
        for (int i = 0; i < 6; i++) {
            int idx = tid + i * 256;      // 0..1535
            int arr = idx / 512;
            int rem = idx & 511;
            int r   = rem >> 2;
            int c8  = (rem & 3) * 8;
            const __half* src;
            int rowbase;
            if (arr == 0)      { src = A;  rowbase = m0 + r; }
            else if (arr == 1) { src = Wh; rowbase = n0 + r; }
            else               { src = Wl; rowbase = n0 + r; }
            uint32_t dst = bb + (uint32_t)arr * TILE_B + (uint32_t)(r * RS + c8) * 2;
            CP_ASYNC16(dst, src + (size_t)rowbase * DIM + k0 + c8);
        }
    };

    const uint32_t a_off = (uint32_t)((wm + (lane & 15)) * RS + ((lane & 16) ? 8 : 0));
    const uint32_t b_off = (uint32_t)((wn + (lane & 7) + ((lane & 16) ? 8 : 0)) * RS
                                      + ((lane & 8) ? 8 : 0));

    const int NC = DIM / BKC;   // 32
    load_chunk(0, 0);
    CP_COMMIT();

    for (int c = 0; c < NC; c++) {
        if (c + 1 < NC) {
            load_chunk(c + 1, (c + 1) & 1);
            CP_COMMIT();
            CP_WAIT1();
        } else {
            CP_WAIT0();
        }
        __syncthreads();

        const uint32_t base = smb + (uint32_t)(c & 1) * STG;

        #pragma unroll
        for (int ks = 0; ks < 2; ks++) {
            const uint32_t kc = (uint32_t)(ks * 16);
            uint32_t ar[4][4], wh[2][4], wl[2][4];
            #pragma unroll
            for (int mt = 0; mt < 4; mt++) {
                uint32_t addr = base + (a_off + (uint32_t)(mt * 16) * RS + kc) * 2;
                LDM_X4(ar[mt][0], ar[mt][1], ar[mt][2], ar[mt][3], addr);
            }
            #pragma unroll
            for (int p = 0; p < 2; p++) {
                uint32_t addr = base + TILE_B + (b_off + (uint32_t)(p * 16) * RS + kc) * 2;
                LDM_X4(wh[p][0], wh[p][1], wh[p][2], wh[p][3], addr);
                LDM_X4(wl[p][0], wl[p][1], wl[p][2], wl[p][3], addr + TILE_B);
            }
            #pragma unroll
            for (int mt = 0; mt < 4; mt++)
                #pragma unroll
                for (int nt = 0; nt < 4; nt++) {
                    uint32_t bh[2] = { wh[nt>>1][(nt&1)*2], wh[nt>>1][(nt&1)*2+1] };
                    uint32_t bl[2] = { wl[nt>>1][(nt&1)*2], wl[nt>>1][(nt&1)*2+1] };
                    mma_f16(acc[mt][nt], ar[mt], bh);
                    mma_f16(acc[mt][nt], ar[mt], bl);
                }
        }
        __syncthreads();
    }

    // ---- epilogue ----
    if (mode == 0) {
        #pragma unroll
        for (int mt = 0; mt < 4; mt++) {
            int row0 = m0 + wm + mt * 16 + g;
            #pragma unroll
            for (int nt = 0; nt < 4; nt++) {
                int col = n0 + wn + nt * 8 + t2;
                *(float2*)(Cf + (size_t)row0 * DIM + col) =
                    make_float2(acc[mt][nt][0], acc[mt][nt][1]);
                *(float2*)(Cf + (size_t)(row0 + 8) * DIM + col) =
                    make_float2(acc[mt][nt][2], acc[mt][nt][3]);
            }
        }
    } else {
        int which = n0 >> 10;
        int n0w = n0 & 1023;
        #pragma unroll
        for (int mt = 0; mt < 4; mt++) {
            int row0 = m0 + wm + mt * 16 + g;
            int bb0 = row0 >> 11, t0 = row0 & (T - 1);
            int bb1 = (row0 + 8) >> 11, t1 = (row0 + 8) & (T - 1);
            #pragma unroll
            for (int nt = 0; nt < 4; nt++) {
                int col = n0w + wn + nt * 8 + t2;
                int h = col >> 6, d = col & 63;
                size_t i0 = (((size_t)bb0 * H + h) * T + t0) * DH + d;
                size_t i1 = (((size_t)bb1 * H + h) * T + t1) * DH + d;
                float a0 = acc[mt][nt][0], a1 = acc[mt][nt][1];
                float a2 = acc[mt][nt][2], a3 = acc[mt][nt][3];
                if (which == 0) {
                    *(uint32_t*)(Cq + i0) = pkh(a0, a1);
                    *(uint32_t*)(Cq + i1) = pkh(a2, a3);
                } else if (which == 2) {
                    *(uint32_t*)(Cv + i0) = pkh(a0, a1);
                    *(uint32_t*)(Cv + i1) = pkh(a2, a3);
                } else {
                    __half h0 = __float2half_rn(a0), h1 = __float2half_rn(a1);
                    __half h2 = __float2half_rn(a2), h3 = __float2half_rn(a3);
                    *(uint32_t*)(Ckh + i0) = pkh(__half2float(h0), __half2float(h1));
                    *(uint32_t*)(Ckh + i1) = pkh(__half2float(h2), __half2float(h3));
                    *(uint32_t*)(Ckl + i0) = pkh(a0 - __half2float(h0), a1 - __half2float(h1));
                    *(uint32_t*)(Ckl + i1) = pkh(a2 - __half2float(h2), a3 - __half2float(h3));
                }
            }
        }
    }
}

// ---------------------------------------------------------------------------
// Tensor-core sliding-window attention, RoPE fused at load.
// Block = (64 queries, h, b); keys [q0-128, q0+63] -> 192.
// smem: Q single fp16 (rope+scale), K hi/lo fp16 (rope), V single fp16.
// S = Qh*Kh + Qh*Kl (2-pass); PV = P*Vh (1-pass). ao written as fp16.
// ---------------------------------------------------------------------------
#define ARS 72
#define AQ  0
#define AKH (64*ARS*2)               // 9216
#define AKL (AKH + 192*ARS*2)        // 36864
#define AV  (AKL + 192*ARS*2)        // 64512
#define ARED (AV + 192*ARS*2)        // 92160
#define ATT_SMEM (ARED + 1024)       // 93184

__global__ __launch_bounds__(256, 2) void attn_hmma(
    const __half* __restrict__ qh,
    const __half* __restrict__ khi, const __half* __restrict__ klo,
    const __half* __restrict__ vh,
    const float* __restrict__ rope,
    __half* __restrict__ ao)
{
    extern __shared__ __align__(16) char sm[];
    const uint32_t smb = smem_u32(sm);
    float* redm = (float*)(sm + ARED);
    float* reds = (float*)(sm + ARED + 512);
    float* scratch = (float*)sm;    // 4096 floats, reused post-softmax

    const int q0 = blockIdx.x * 64;
    const int h  = blockIdx.y;
    const int bb = blockIdx.z;
    const int tid = threadIdx.x;
    const int wid = tid >> 5;
    const int lane = tid & 31;
    const size_t headbase = ((size_t)bb * H + h) * T * DH;
    const int k0 = q0 - 128;

    // ---- load phase: rope Q (scale folded) and K; copy V ----
    for (int task = tid; task < 2048; task += 256) {
        bool isQ = task < 512;
        int lt = isQ ? task : task - 512;
        int r  = lt >> 3;
        int dg = (lt & 7) * 4;
        int rowt;
        if (isQ) rowt = q0 + r;
        else {
            int kg = k0 + r;
            rowt = kg < 0 ? 0 : (kg >= T ? T - 1 : kg);
        }
        size_t ib = headbase + (size_t)rowt * DH;
        float x1[4], x2[4];
        if (isQ) {
            ld4h(qh + ib + dg, x1);
            ld4h(qh + ib + dg + 32, x2);
        } else {
            float a1[4], a2[4], b1[4], b2[4];
            ld4h(khi + ib + dg, a1);      ld4h(klo + ib + dg, b1);
            ld4h(khi + ib + dg + 32, a2); ld4h(klo + ib + dg + 32, b2);
            #pragma unroll
            for (int e = 0; e < 4; e++) { x1[e] = a1[e] + b1[e]; x2[e] = a2[e] + b2[e]; }
        }
        const float* pr = rope + ((size_t)bb * T + rowt) * DH;
        float4 pa = *(const float4*)(pr + dg);
        float4 pb = *(const float4*)(pr + dg + 32);
        float p1[4] = {pa.x, pa.y, pa.z, pa.w};
        float p2[4] = {pb.x, pb.y, pb.z, pb.w};
        float y1[4], y2[4];
        #pragma unroll
        for (int e = 0; e < 4; e++) {
            float c1 = cosf(p1[e]), s1 = sinf(p1[e]);
            float c2 = cosf(p2[e]), s2 = sinf(p2[e]);
            y1[e] = x1[e] * c1 - x2[e] * s1;
            y2[e] = x2[e] * c2 + x1[e] * s2;
        }
        if (isQ) {
            #pragma unroll
            for (int e = 0; e < 4; e++) { y1[e] *= ATT_SCALE; y2[e] *= ATT_SCALE; }
            uint32_t b0 = (uint32_t)(r * ARS);
            *(uint32_t*)(sm + AQ + (b0 + dg) * 2)      = pkh(y1[0], y1[1]);
            *(uint32_t*)(sm + AQ + (b0 + dg + 2) * 2)  = pkh(y1[2], y1[3]);
            *(uint32_t*)(sm + AQ + (b0 + dg + 32) * 2) = pkh(y2[0], y2[1]);
            *(uint32_t*)(sm + AQ + (b0 + dg + 34) * 2) = pkh(y2[2], y2[3]);
        } else {
            float r1[4], r2[4];
            __half h1[4], h2[4];
            #pragma unroll
            for (int e = 0; e < 4; e++) {
                h1[e] = __float2half_rn(y1[e]); r1[e] = y1[e] - __half2float(h1[e]);
                h2[e] = __float2half_rn(y2[e]); r2[e] = y2[e] - __half2float(h2[e]);
            }
            uint32_t b0 = (uint32_t)(r * ARS);
            *(uint32_t*)(sm + AKH + (b0 + dg) * 2)      = pkh(__half2float(h1[0]), __half2float(h1[1]));
            *(uint32_t*)(sm + AKH + (b0 + dg + 2) * 2)  = pkh(__half2float(h1[2]), __half2float(h1[3]));
            *(uint32_t*)(sm + AKH + (b0 + dg + 32) * 2) = pkh(__half2float(h2[0]), __half2float(h2[1]));
            *(uint32_t*)(sm + AKH + (b0 + dg + 34) * 2) = pkh(__half2float(h2[2]), __half2float(h2[3]));
            *(uint32_t*)(sm + AKL + (b0 + dg) * 2)      = pkh(r1[0], r1[1]);
            *(uint32_t*)(sm + AKL + (b0 + dg + 2) * 2)  = pkh(r1[2], r1[3]);
            *(uint32_t*)(sm + AKL + (b0 + dg + 32) * 2) = pkh(r2[0], r2[1]);
            *(uint32_t*)(sm + AKL + (b0 + dg + 34) * 2) = pkh(r2[2], r2[3]);
        }
    }
    for (int task = tid; task < 1536; task += 256) {
        int r = task >> 3, s = task & 7;
        int kg = k0 + r;
        int kc = kg < 0 ? 0 : (kg >= T ? T - 1 : kg);
        *(uint4*)(sm + AV + (uint32_t)(r * ARS + s * 8) * 2) =
            *(const uint4*)(vh + headbase + (size_t)kc * DH + s * 8);
    }
    __syncthreads();

    const int mt   = wid & 3;
    const int half = wid >> 2;
    const int row_r = lane >> 2;

    // ---- S = Q K^T ----
    float p[12][4];
    #pragma unroll
    for (int nt = 0; nt < 12; nt++)
        #pragma unroll
        for (int e = 0; e < 4; e++) p[nt][e] = 0.f;

    const uint32_t qa_off = (uint32_t)((mt * 16 + (lane & 15)) * ARS
                                       + ((lane & 16) ? 8 : 0)) * 2;
    const uint32_t kb_row = (uint32_t)(half * 96 + (lane & 7) + ((lane & 16) ? 8 : 0));
    const uint32_t kb_coff = (uint32_t)((lane & 8) ? 8 : 0);

    #pragma unroll
    for (int kt = 0; kt < 4; kt++) {
        const uint32_t kc = (uint32_t)(kt * 16);
        uint32_t aq[4];
        LDM_X4(aq[0], aq[1], aq[2], aq[3], smb + AQ + qa_off + kc * 2);
        #pragma unroll
        for (int pp = 0; pp < 6; pp++) {
            uint32_t addr = smb + AKH
                + ((kb_row + (uint32_t)(pp * 16)) * ARS + kc + kb_coff) * 2;
            uint32_t bh[4], bl[4];
            LDM_X4(bh[0], bh[1], bh[2], bh[3], addr);
            LDM_X4(bl[0], bl[1], bl[2], bl[3], addr + (AKL - AKH));
            #pragma unroll
            for (int sub = 0; sub < 2; sub++) {
                int nt = pp * 2 + sub;
                uint32_t bbh[2] = { bh[sub*2], bh[sub*2+1] };
                uint32_t bbl[2] = { bl[sub*2], bl[sub*2+1] };
                mma_f16(p[nt], aq, bbh);
                mma_f16(p[nt], aq, bbl);
            }
        }
    }

    // ---- mask (scale already folded into Q) ----
    {
        int qg1 = q0 + mt * 16 + row_r;
        int qg2 = qg1 + 8;
        #pragma unroll
        for (int nt = 0; nt < 12; nt++) {
            int cb = k0 + half * 96 + nt * 8 + 2 * (lane & 3);
            #pragma unroll
            for (int e = 0; e < 4; e++) {
                int kg = cb + (e & 1);
                int qg = (e & 2) ? qg2 : qg1;
                bool valid = (kg >= 0) && (kg <= qg) && (kg >= qg - 128);
                if (!valid) p[nt][e] = -1e30f;
            }
        }
    }

    // ---- softmax (cross-half via smem) ----
    float inv1, inv2;
    {
        float m0v = -1e30f, m1v = -1e30f;
        #pragma unroll
        for (int nt = 0; nt < 12; nt++) {
            m0v = fmaxf(m0v, fmaxf(p[nt][0], p[nt][1]));
            m1v = fmaxf(m1v, fmaxf(p[nt][2], p[nt][3]));
        }
        m0v = fmaxf(m0v, __shfl_xor_sync(0xffffffffu, m0v, 1));
        m0v = fmaxf(m0v, __shfl_xor_sync(0xffffffffu, m0v, 2));
        m1v = fmaxf(m1v, __shfl_xor_sync(0xffffffffu, m1v, 1));
        m1v = fmaxf(m1v, __shfl_xor_sync(0xffffffffu, m1v, 2));
        if ((lane & 3) == 0) {
            redm[half * 64 + mt * 16 + row_r]     = m0v;
            redm[half * 64 + mt * 16 + row_r + 8] = m1v;
        }
        __syncthreads();
        float M0 = fmaxf(redm[mt*16 + row_r],     redm[64 + mt*16 + row_r]);
        float M1 = fmaxf(redm[mt*16 + row_r + 8], redm[64 + mt*16 + row_r + 8]);

        float s0 = 0.f, s1 = 0.f;
        #pragma unroll
        for (int nt = 0; nt < 12; nt++) {
            p[nt][0] = __expf(p[nt][0] - M0); s0 += p[nt][0];
            p[nt][1] = __expf(p[nt][1] - M0); s0 += p[nt][1];
            p[nt][2] = __expf(p[nt][2] - M1); s1 += p[nt][2];
            p[nt][3] = __expf(p[nt][3] - M1); s1 += p[nt][3];
        }
        s0 += __shfl_xor_sync(0xffffffffu, s0, 1);
        s0 += __shfl_xor_sync(0xffffffffu, s0, 2);
        s1 += __shfl_xor_sync(0xffffffffu, s1, 1);
        s1 += __shfl_xor_sync(0xffffffffu, s1, 2);
        if ((lane & 3) == 0) {
            reds[half * 64 + mt * 16 + row_r]     = s0;
            reds[half * 64 + mt * 16 + row_r + 8] = s1;
        }
        __syncthreads();
        inv1 = 1.0f / (reds[mt*16 + row_r]     + reds[64 + mt*16 + row_r]);
        inv2 = 1.0f / (reds[mt*16 + row_r + 8] + reds[64 + mt*16 + row_r + 8]);
    }

    // ---- O = P V (single pass, ldmatrix.trans on V) ----
    float o[8][4];
    #pragma unroll
    for (int nt = 0; nt < 8; nt++)
        #pragma unroll
        for (int e = 0; e < 4; e++) o[nt][e] = 0.f;

    const uint32_t vb_row = (uint32_t)(half * 96 + (lane & 7) + ((lane & 8) ? 8 : 0));
    const uint32_t vb_coff = (uint32_t)((lane & 16) ? 8 : 0);

    #pragma unroll
    for (int kt = 0; kt < 6; kt++) {
        uint32_t pa[4];
        {
            float* e0 = p[2*kt]; float* e1 = p[2*kt+1];
            pa[0] = pkh(e0[0], e0[1]);
            pa[1] = pkh(e0[2], e0[3]);
            pa[2] = pkh(e1[0], e1[1]);
            pa[3] = pkh(e1[2], e1[3]);
        }
        #pragma unroll
        for (int dp = 0; dp < 4; dp++) {
            uint32_t addr = smb + AV
                + ((vb_row + (uint32_t)(kt * 16)) * ARS + (uint32_t)(dp * 16) + vb_coff) * 2;
            uint32_t vv[4];
            LDM_X4_T(vv[0], vv[1], vv[2], vv[3], addr);
            #pragma unroll
            for (int sub = 0; sub < 2; sub++) {
                int nt = dp * 2 + sub;
                uint32_t bb2[2] = { vv[sub*2], vv[sub*2+1] };
                mma_f16(o[nt], pa, bb2);
            }
        }
    }

    // ---- combine halves, write ao as fp16 ----
    if (half == 1) {
        #pragma unroll
        for (int nt = 0; nt < 8; nt++) {
            int col = nt * 8 + 2 * (lane & 3);
            *(float2*)&scratch[mt * 1024 + row_r * 64 + col] =
                make_float2(o[nt][0], o[nt][1]);
            *(float2*)&scratch[mt * 1024 + (row_r + 8) * 64 + col] =
                make_float2(o[nt][2], o[nt][3]);
        }
    }
    __syncthreads();
    if (half == 0) {
        int r1g = q0 + mt * 16 + row_r;
        int r2g = r1g + 8;
        #pragma unroll
        for (int nt = 0; nt < 8; nt++) {
            int col = nt * 8 + 2 * (lane & 3);
            float2 s1v = *(float2*)&scratch[mt * 1024 + row_r * 64 + col];
            float2 s2v = *(float2*)&scratch[mt * 1024 + (row_r + 8) * 64 + col];
            float w10 = (o[nt][0] + s1v.x) * inv1, w11 = (o[nt][1] + s1v.y) * inv1;
            float w20 = (o[nt][2] + s2v.x) * inv2, w21 = (o[nt][3] + s2v.y) * inv2;
            *(uint32_t*)(ao + ((size_t)bb * T + r1g) * DIM + h * 64 + col) = pkh(w10, w11);
            *(uint32_t*)(ao + ((size_t)bb * T + r2g) * DIM + h * 64 + col) = pkh(w20, w21);
        }
    }
}

// ---------------------------------------------------------------------------
extern "C" void kernel_launch(void* const* d_in, const int* in_sizes, int n_in,
                              void* d_out, int out_size)
{
    const float* x    = (const float*)d_in[0];
    const float* rope = (const float*)d_in[2];
    const float* Wq   = (const float*)d_in[3];
    const float* Wk   = (const float*)d_in[4];
    const float* Wv   = (const float*)d_in[5];
    const float* Wo   = (const float*)d_in[6];
    float* out = (float*)d_out;

    __half *xh, *whi, *wlo, *qh, *khi, *klo, *vh, *aoh;
    cudaGetSymbolAddress((void**)&xh,  g_xh);
    cudaGetSymbolAddress((void**)&whi, g_whi);
    cudaGetSymbolAddress((void**)&wlo, g_wlo);
    cudaGetSymbolAddress((void**)&qh,  g_qh);
    cudaGetSymbolAddress((void**)&khi, g_khi);
    cudaGetSymbolAddress((void**)&klo, g_klo);
    cudaGetSymbolAddress((void**)&vh,  g_vh);
    cudaGetSymbolAddress((void**)&aoh, g_aoh);

    cudaFuncSetAttribute(gemm_hmma, cudaFuncAttributeMaxDynamicSharedMemorySize, GEMM_SMEM);
    cudaFuncSetAttribute(attn_hmma, cudaFuncAttributeMaxDynamicSharedMemorySize, ATT_SMEM);

    const int xn4 = XSZ / 4;       // 1048576
    const int wn4tot = 4 * WSZ / 4;

    tohalf<<<xn4 / 256, 256>>>(x, xh, xn4);
    split_w4<<<wn4tot / 256, 256>>>(Wq, Wk, Wv, Wo, whi, wlo);

    // fused QKV (N = 3072)
    gemm_hmma<<<dim3(24, 32), 256, GEMM_SMEM>>>(xh, whi, wlo,
                                                nullptr, qh, khi, klo, vh, 1);

    attn_hmma<<<dim3(T / 64, H, B), 256, ATT_SMEM>>>(qh, khi, klo, vh, rope, aoh);

    // O projection (W index 3)
    gemm_hmma<<<dim3(8, 32), 256, GEMM_SMEM>>>(aoh, whi + 3*(size_t)WSZ, wlo + 3*(size_t)WSZ,
                                               out, nullptr, nullptr, nullptr, nullptr, 0);
}

// round 8
// speedup vs baseline: 2.1207x; 2.1207x over previous
#include <cuda_runtime.h>
#include <cuda_fp16.h>
#include <math.h>
#include <stdint.h>

#define B 2
#define T 2048
#define H 16
#define DH 64
#define DIM 1024
#define M_TOTAL (B*T)      // 4096
#define SZH (B*H*T*DH)     // 4194304
#define XSZ (M_TOTAL*DIM)  // 4194304
#define WSZ (DIM*DIM)      // 1048576
#define ATT_SCALE 0.125f

// ---------------- scratch (device globals; allocation-free) ----------------
__device__ __half g_xh [XSZ];
__device__ __half g_whi[4*WSZ];
__device__ __half g_wlo[4*WSZ];
__device__ __half g_qh [SZH];
__device__ __half g_khi[SZH];
__device__ __half g_klo[SZH];
__device__ __half g_vh [SZH];
__device__ __half g_aoh[XSZ];

// ---------------- helpers ----------------
__device__ __forceinline__ uint32_t smem_u32(const void* p) {
    uint32_t a;
    asm("{ .reg .u64 t; cvta.to.shared.u64 t, %1; cvt.u32.u64 %0, t; }"
        : "=r"(a) : "l"(p));
    return a;
}

#define CP_ASYNC16(dst_u32, src_ptr) \
    asm volatile("cp.async.cg.shared.global [%0], [%1], 16;" :: "r"(dst_u32), "l"(src_ptr))
#define CP_COMMIT()  asm volatile("cp.async.commit_group;" ::: "memory")
#define CP_WAIT0()   asm volatile("cp.async.wait_group 0;" ::: "memory")
#define CP_WAIT1()   asm volatile("cp.async.wait_group 1;" ::: "memory")

#define LDM_X4(r0,r1,r2,r3, addr) \
    asm volatile("ldmatrix.sync.aligned.m8n8.x4.shared.b16 {%0,%1,%2,%3}, [%4];" \
                 : "=r"(r0), "=r"(r1), "=r"(r2), "=r"(r3) : "r"(addr))
#define LDM_X4_T(r0,r1,r2,r3, addr) \
    asm volatile("ldmatrix.sync.aligned.m8n8.x4.trans.shared.b16 {%0,%1,%2,%3}, [%4];" \
                 : "=r"(r0), "=r"(r1), "=r"(r2), "=r"(r3) : "r"(addr))

__device__ __forceinline__ void mma_f16(float* c, const uint32_t* a, const uint32_t* b) {
    asm volatile(
        "mma.sync.aligned.m16n8k16.row.col.f32.f16.f16.f32 "
        "{%0,%1,%2,%3}, {%4,%5,%6,%7}, {%8,%9}, {%0,%1,%2,%3};"
        : "+f"(c[0]), "+f"(c[1]), "+f"(c[2]), "+f"(c[3])
        : "r"(a[0]), "r"(a[1]), "r"(a[2]), "r"(a[3]), "r"(b[0]), "r"(b[1]));
}

__device__ __forceinline__ uint32_t pkh(float a, float b) {
    __half2 t = __floats2half2_rn(a, b);
    return *(uint32_t*)&t;
}

// ---------------------------------------------------------------------------
// fp32 -> fp16 (single)
// ---------------------------------------------------------------------------
__global__ void tohalf(const float* __restrict__ x, __half* __restrict__ o, int n4)
{
    int i = blockIdx.x * blockDim.x + threadIdx.x;
    if (i >= n4) return;
    float4 v = ((const float4*)x)[i];
    uint2 u;
    u.x = pkh(v.x, v.y);
    u.y = pkh(v.z, v.w);
    *(uint2*)(o + 4 * (size_t)i) = u;
}

// ---------------------------------------------------------------------------
// 4 weight matrices -> fp16 hi/lo (one launch)
// ---------------------------------------------------------------------------
__global__ void split_w4(const float* __restrict__ W0, const float* __restrict__ W1,
                         const float* __restrict__ W2, const float* __restrict__ W3,
                         __half* __restrict__ hi, __half* __restrict__ lo)
{
    int i = blockIdx.x * blockDim.x + threadIdx.x;  // over 4*WSZ/4
    int which = i >> 18;                            // WSZ/4 = 2^18
    int j = i & 0x3FFFF;
    const float* W = (which == 0) ? W0 : (which == 1) ? W1 : (which == 2) ? W2 : W3;
    float4 v = ((const float4*)W)[j];
    float f[4] = {v.x, v.y, v.z, v.w};
    float r[4];
    __half h[4];
    #pragma unroll
    for (int e = 0; e < 4; e++) {
        h[e] = __float2half_rn(f[e]);
        r[e] = f[e] - __half2float(h[e]);
    }
    size_t base = (size_t)which * WSZ + (size_t)j * 4;
    uint2 uh, ul;
    uh.x = pkh(__half2float(h[0]), __half2float(h[1]));
    uh.y = pkh(__half2float(h[2]), __half2float(h[3]));
    ul.x = pkh(r[0], r[1]);
    ul.y = pkh(r[2], r[3]);
    *(uint2*)(hi + base) = uh;
    *(uint2*)(lo + base) = ul;
}

// ---------------------------------------------------------------------------
// RoPE prep (IN-PLACE): ropes Q (folds ATT_SCALE) and K (hi/lo re-split).
// Each thread owns the disjoint (d, d+32) pair of one (b,h,t) row.
// ---------------------------------------------------------------------------
__global__ void rope_prep(__half* __restrict__ q,
                          __half* __restrict__ khi, __half* __restrict__ klo,
                          const float* __restrict__ rope)
{
    int idx = blockIdx.x * blockDim.x + threadIdx.x;   // B*H*T*32
    if (idx >= B * H * T * 32) return;
    int d    = idx & 31;
    int rest = idx >> 5;               // (b*H+h)*T + t
    int t    = rest & (T - 1);
    int bh   = rest >> 11;
    int bidx = bh >> 4;

    const float* pr = rope + ((size_t)bidx * T + t) * DH;
    float p1 = pr[d], p2 = pr[d + 32];
    float c1, s1, c2, s2;
    __sincosf(p1, &s1, &c1);
    __sincosf(p2, &s2, &c2);

    size_t base = (size_t)rest * DH;
    // Q (scale folded)
    float x1 = __half2float(q[base + d]);
    float x2 = __half2float(q[base + d + 32]);
    q[base + d]      = __float2half_rn((x1 * c1 - x2 * s1) * ATT_SCALE);
    q[base + d + 32] = __float2half_rn((x2 * c2 + x1 * s2) * ATT_SCALE);
    // K (reconstruct, rope, re-split)
    float k1 = __half2float(khi[base + d])      + __half2float(klo[base + d]);
    float k2 = __half2float(khi[base + d + 32]) + __half2float(klo[base + d + 32]);
    float y1 = k1 * c1 - k2 * s1;
    float y2 = k2 * c2 + k1 * s2;
    __half h1 = __float2half_rn(y1), h2 = __float2half_rn(y2);
    khi[base + d]      = h1;
    klo[base + d]      = __float2half_rn(y1 - __half2float(h1));
    khi[base + d + 32] = h2;
    klo[base + d + 32] = __float2half_rn(y2 - __half2float(h2));
}

// ---------------------------------------------------------------------------
// Tensor-core GEMM: C[m,n] = sum_k A[m,k]*W[n,k]
// A single fp16; W fp16 hi/lo (2-pass).
// mode 0: Cf fp32 row-major (N=DIM, grid.x=8)
// mode 1: QKV fused (grid.x=24): which=n0>>10 -> Q single / K hi,lo / V single
// ---------------------------------------------------------------------------
#define BKC 32
#define RS  40
#define TILE_B (128*RS*2)          // 10240 bytes
#define STG (3*TILE_B)             // A, Wh, Wl
#define GEMM_SMEM (2*STG)          // 61440

__global__ __launch_bounds__(256) void gemm_hmma(
    const __half* __restrict__ A,
    const __half* __restrict__ Wh, const __half* __restrict__ Wl,
    float* __restrict__ Cf,
    __half* __restrict__ Cq, __half* __restrict__ Ckh,
    __half* __restrict__ Ckl, __half* __restrict__ Cv,
    int mode)
{
    extern __shared__ __align__(16) char sm[];
    const uint32_t smb = smem_u32(sm);

    const int tid  = threadIdx.x;
    const int m0   = blockIdx.y * 128;
    const int n0   = blockIdx.x * 128;
    const int wid  = tid >> 5;
    const int lane = tid & 31;
    const int g    = lane >> 2;
    const int t2   = (lane & 3) * 2;
    const int wm   = (wid & 1) * 64;
    const int wn   = (wid >> 1) * 32;

    float acc[4][4][4];
    #pragma unroll
    for (int mt = 0; mt < 4; mt++)
        #pragma unroll
        for (int nt = 0; nt < 4; nt++)
            #pragma unroll
            for (int e = 0; e < 4; e++) acc[mt][nt][e] = 0.f;

    auto load_chunk = [&](int c, int buf) {
        const int k0 = c * BKC;
        const uint32_t bb = smb + (uint32_t)buf * STG;
        #pragma unroll
        for (int i = 0; i < 6; i++) {
            int idx = tid + i * 256;      // 0..1535
            int arr = idx / 512;
            int rem = idx & 511;
            int r   = rem >> 2;
            int c8  = (rem & 3) * 8;
            const __half* src;
            int rowbase;
            if (arr == 0)      { src = A;  rowbase = m0 + r; }
            else if (arr == 1) { src = Wh; rowbase = n0 + r; }
            else               { src = Wl; rowbase = n0 + r; }
            uint32_t dst = bb + (uint32_t)arr * TILE_B + (uint32_t)(r * RS + c8) * 2;
            CP_ASYNC16(dst, src + (size_t)rowbase * DIM + k0 + c8);
        }
    };

    const uint32_t a_off = (uint32_t)((wm + (lane & 15)) * RS + ((lane & 16) ? 8 : 0));
    const uint32_t b_off = (uint32_t)((wn + (lane & 7) + ((lane & 16) ? 8 : 0)) * RS
                                      + ((lane & 8) ? 8 : 0));

    const int NC = DIM / BKC;   // 32
    load_chunk(0, 0);
    CP_COMMIT();

    for (int c = 0; c < NC; c++) {
        if (c + 1 < NC) {
            load_chunk(c + 1, (c + 1) & 1);
            CP_COMMIT();
            CP_WAIT1();
        } else {
            CP_WAIT0();
        }
        __syncthreads();

        const uint32_t base = smb + (uint32_t)(c & 1) * STG;

        #pragma unroll
        for (int ks = 0; ks < 2; ks++) {
            const uint32_t kc = (uint32_t)(ks * 16);
            uint32_t ar[4][4], wh[2][4], wl[2][4];
            #pragma unroll
            for (int mt = 0; mt < 4; mt++) {
                uint32_t addr = base + (a_off + (uint32_t)(mt * 16) * RS + kc) * 2;
                LDM_X4(ar[mt][0], ar[mt][1], ar[mt][2], ar[mt][3], addr);
            }
            #pragma unroll
            for (int p = 0; p < 2; p++) {
                uint32_t addr = base + TILE_B + (b_off + (uint32_t)(p * 16) * RS + kc) * 2;
                LDM_X4(wh[p][0], wh[p][1], wh[p][2], wh[p][3], addr);
                LDM_X4(wl[p][0], wl[p][1], wl[p][2], wl[p][3], addr + TILE_B);
            }
            #pragma unroll
            for (int mt = 0; mt < 4; mt++)
                #pragma unroll
                for (int nt = 0; nt < 4; nt++) {
                    uint32_t bh[2] = { wh[nt>>1][(nt&1)*2], wh[nt>>1][(nt&1)*2+1] };
                    uint32_t bl[2] = { wl[nt>>1][(nt&1)*2], wl[nt>>1][(nt&1)*2+1] };
                    mma_f16(acc[mt][nt], ar[mt], bh);
                    mma_f16(acc[mt][nt], ar[mt], bl);
                }
        }
        __syncthreads();
    }

    // ---- epilogue ----
    if (mode == 0) {
        #pragma unroll
        for (int mt = 0; mt < 4; mt++) {
            int row0 = m0 + wm + mt * 16 + g;
            #pragma unroll
            for (int nt = 0; nt < 4; nt++) {
                int col = n0 + wn + nt * 8 + t2;
                *(float2*)(Cf + (size_t)row0 * DIM + col) =
                    make_float2(acc[mt][nt][0], acc[mt][nt][1]);
                *(float2*)(Cf + (size_t)(row0 + 8) * DIM + col) =
                    make_float2(acc[mt][nt][2], acc[mt][nt][3]);
            }
        }
    } else {
        int which = n0 >> 10;
        int n0w = n0 & 1023;
        #pragma unroll
        for (int mt = 0; mt < 4; mt++) {
            int row0 = m0 + wm + mt * 16 + g;
            int bb0 = row0 >> 11, t0 = row0 & (T - 1);
            int bb1 = (row0 + 8) >> 11, t1 = (row0 + 8) & (T - 1);
            #pragma unroll
            for (int nt = 0; nt < 4; nt++) {
                int col = n0w + wn + nt * 8 + t2;
                int h = col >> 6, d = col & 63;
                size_t i0 = (((size_t)bb0 * H + h) * T + t0) * DH + d;
                size_t i1 = (((size_t)bb1 * H + h) * T + t1) * DH + d;
                float a0 = acc[mt][nt][0], a1 = acc[mt][nt][1];
                float a2 = acc[mt][nt][2], a3 = acc[mt][nt][3];
                if (which == 0) {
                    *(uint32_t*)(Cq + i0) = pkh(a0, a1);
                    *(uint32_t*)(Cq + i1) = pkh(a2, a3);
                } else if (which == 2) {
                    *(uint32_t*)(Cv + i0) = pkh(a0, a1);
                    *(uint32_t*)(Cv + i1) = pkh(a2, a3);
                } else {
                    __half h0 = __float2half_rn(a0), h1 = __float2half_rn(a1);
                    __half h2 = __float2half_rn(a2), h3 = __float2half_rn(a3);
                    *(uint32_t*)(Ckh + i0) = pkh(__half2float(h0), __half2float(h1));
                    *(uint32_t*)(Ckh + i1) = pkh(__half2float(h2), __half2float(h3));
                    *(uint32_t*)(Ckl + i0) = pkh(a0 - __half2float(h0), a1 - __half2float(h1));
                    *(uint32_t*)(Ckl + i1) = pkh(a2 - __half2float(h2), a3 - __half2float(h3));
                }
            }
        }
    }
}

// ---------------------------------------------------------------------------
// Tensor-core sliding-window attention. Pre-roped inputs; load = pure cp.async.
// Block = (64 queries, h, b); keys [q0-128, q0+63] -> 192.
// S = Q*Kh + Q*Kl (2-pass); PV = P*V (1-pass). ao written as fp16.
// ---------------------------------------------------------------------------
#define ARS 72
#define AQ  0
#define AKH (64*ARS*2)               // 9216
#define AKL (AKH + 192*ARS*2)        // 36864
#define AV  (AKL + 192*ARS*2)        // 64512
#define ARED (AV + 192*ARS*2)        // 92160
#define ATT_SMEM (ARED + 1024)       // 93184

__global__ __launch_bounds__(256, 2) void attn_hmma(
    const __half* __restrict__ qh,
    const __half* __restrict__ khi, const __half* __restrict__ klo,
    const __half* __restrict__ vh,
    __half* __restrict__ ao)
{
    extern __shared__ __align__(16) char sm[];
    const uint32_t smb = smem_u32(sm);
    float* redm = (float*)(sm + ARED);
    float* reds = (float*)(sm + ARED + 512);
    float* scratch = (float*)sm;    // 16KB, reused post-S-phase

    const int q0 = blockIdx.x * 64;
    const int h  = blockIdx.y;
    const int bb = blockIdx.z;
    const int tid = threadIdx.x;
    const int wid = tid >> 5;
    const int lane = tid & 31;
    const size_t headbase = ((size_t)bb * H + h) * T * DH;
    const int k0 = q0 - 128;

    // ---- load: pure cp.async (Q 512, K/V 3x1536 16B copies) ----
    for (int i = tid; i < 512; i += 256) {
        int r = i >> 3, s = i & 7;
        CP_ASYNC16(smb + AQ + (uint32_t)(r * ARS + s * 8) * 2,
                   qh + headbase + (size_t)(q0 + r) * DH + s * 8);
    }
    for (int i = tid; i < 1536; i += 256) {
        int r = i >> 3, s = i & 7;
        int kg = k0 + r;
        int kc = kg < 0 ? 0 : (kg >= T ? T - 1 : kg);
        size_t src = headbase + (size_t)kc * DH + s * 8;
        uint32_t off = (uint32_t)(r * ARS + s * 8) * 2;
        CP_ASYNC16(smb + AKH + off, khi + src);
        CP_ASYNC16(smb + AKL + off, klo + src);
        CP_ASYNC16(smb + AV  + off, vh  + src);
    }
    CP_COMMIT();
    CP_WAIT0();
    __syncthreads();

    const int mt   = wid & 3;
    const int half = wid >> 2;
    const int row_r = lane >> 2;

    // ---- S = Q K^T (2-pass: Kh then Kl) ----
    float p[12][4];
    #pragma unroll
    for (int nt = 0; nt < 12; nt++)
        #pragma unroll
        for (int e = 0; e < 4; e++) p[nt][e] = 0.f;

    const uint32_t qa_off = (uint32_t)((mt * 16 + (lane & 15)) * ARS
                                       + ((lane & 16) ? 8 : 0)) * 2;
    const uint32_t kb_row = (uint32_t)(half * 96 + (lane & 7) + ((lane & 16) ? 8 : 0));
    const uint32_t kb_coff = (uint32_t)((lane & 8) ? 8 : 0);

    #pragma unroll
    for (int kt = 0; kt < 4; kt++) {
        const uint32_t kc = (uint32_t)(kt * 16);
        uint32_t aq[4];
        LDM_X4(aq[0], aq[1], aq[2], aq[3], smb + AQ + qa_off + kc * 2);
        #pragma unroll
        for (int pp = 0; pp < 6; pp++) {
            uint32_t addr = smb + AKH
                + ((kb_row + (uint32_t)(pp * 16)) * ARS + kc + kb_coff) * 2;
            uint32_t bh[4], bl[4];
            LDM_X4(bh[0], bh[1], bh[2], bh[3], addr);
            LDM_X4(bl[0], bl[1], bl[2], bl[3], addr + (AKL - AKH));
            #pragma unroll
            for (int sub = 0; sub < 2; sub++) {
                int nt = pp * 2 + sub;
                uint32_t bbh[2] = { bh[sub*2], bh[sub*2+1] };
                uint32_t bbl[2] = { bl[sub*2], bl[sub*2+1] };
                mma_f16(p[nt], aq, bbh);
                mma_f16(p[nt], aq, bbl);
            }
        }
    }

    // ---- mask (scale folded into Q at prep) ----
    {
        int qg1 = q0 + mt * 16 + row_r;
        int qg2 = qg1 + 8;
        #pragma unroll
        for (int nt = 0; nt < 12; nt++) {
            int cb = k0 + half * 96 + nt * 8 + 2 * (lane & 3);
            #pragma unroll
            for (int e = 0; e < 4; e++) {
                int kg = cb + (e & 1);
                int qg = (e & 2) ? qg2 : qg1;
                bool valid = (kg >= 0) && (kg <= qg) && (kg >= qg - 128);
                if (!valid) p[nt][e] = -1e30f;
            }
        }
    }

    // ---- softmax (cross-half via smem) ----
    float inv1, inv2;
    {
        float m0v = -1e30f, m1v = -1e30f;
        #pragma unroll
        for (int nt = 0; nt < 12; nt++) {
            m0v = fmaxf(m0v, fmaxf(p[nt][0], p[nt][1]));
            m1v = fmaxf(m1v, fmaxf(p[nt][2], p[nt][3]));
        }
        m0v = fmaxf(m0v, __shfl_xor_sync(0xffffffffu, m0v, 1));
        m0v = fmaxf(m0v, __shfl_xor_sync(0xffffffffu, m0v, 2));
        m1v = fmaxf(m1v, __shfl_xor_sync(0xffffffffu, m1v, 1));
        m1v = fmaxf(m1v, __shfl_xor_sync(0xffffffffu, m1v, 2));
        if ((lane & 3) == 0) {
            redm[half * 64 + mt * 16 + row_r]     = m0v;
            redm[half * 64 + mt * 16 + row_r + 8] = m1v;
        }
        __syncthreads();
        float M0 = fmaxf(redm[mt*16 + row_r],     redm[64 + mt*16 + row_r]);
        float M1 = fmaxf(redm[mt*16 + row_r + 8], redm[64 + mt*16 + row_r + 8]);

        float s0 = 0.f, s1 = 0.f;
        #pragma unroll
        for (int nt = 0; nt < 12; nt++) {
            p[nt][0] = __expf(p[nt][0] - M0); s0 += p[nt][0];
            p[nt][1] = __expf(p[nt][1] - M0); s0 += p[nt][1];
            p[nt][2] = __expf(p[nt][2] - M1); s1 += p[nt][2];
            p[nt][3] = __expf(p[nt][3] - M1); s1 += p[nt][3];
        }
        s0 += __shfl_xor_sync(0xffffffffu, s0, 1);
        s0 += __shfl_xor_sync(0xffffffffu, s0, 2);
        s1 += __shfl_xor_sync(0xffffffffu, s1, 1);
        s1 += __shfl_xor_sync(0xffffffffu, s1, 2);
        if ((lane & 3) == 0) {
            reds[half * 64 + mt * 16 + row_r]     = s0;
            reds[half * 64 + mt * 16 + row_r + 8] = s1;
        }
        __syncthreads();
        inv1 = 1.0f / (reds[mt*16 + row_r]     + reds[64 + mt*16 + row_r]);
        inv2 = 1.0f / (reds[mt*16 + row_r + 8] + reds[64 + mt*16 + row_r + 8]);
    }

    // ---- O = P V (single pass, ldmatrix.trans on V) ----
    float o[8][4];
    #pragma unroll
    for (int nt = 0; nt < 8; nt++)
        #pragma unroll
        for (int e = 0; e < 4; e++) o[nt][e] = 0.f;

    const uint32_t vb_row = (uint32_t)(half * 96 + (lane & 7) + ((lane & 8) ? 8 : 0));
    const uint32_t vb_coff = (uint32_t)((lane & 16) ? 8 : 0);

    #pragma unroll
    for (int kt = 0; kt < 6; kt++) {
        uint32_t pa[4];
        {
            float* e0 = p[2*kt]; float* e1 = p[2*kt+1];
            pa[0] = pkh(e0[0], e0[1]);
            pa[1] = pkh(e0[2], e0[3]);
            pa[2] = pkh(e1[0], e1[1]);
            pa[3] = pkh(e1[2], e1[3]);
        }
        #pragma unroll
        for (int dp = 0; dp < 4; dp++) {
            uint32_t addr = smb + AV
                + ((vb_row + (uint32_t)(kt * 16)) * ARS + (uint32_t)(dp * 16) + vb_coff) * 2;
            uint32_t vv[4];
            LDM_X4_T(vv[0], vv[1], vv[2], vv[3], addr);
            #pragma unroll
            for (int sub = 0; sub < 2; sub++) {
                int nt = dp * 2 + sub;
                uint32_t bb2[2] = { vv[sub*2], vv[sub*2+1] };
                mma_f16(o[nt], pa, bb2);
            }
        }
    }

    // ---- combine halves, write ao as fp16 ----
    if (half == 1) {
        #pragma unroll
        for (int nt = 0; nt < 8; nt++) {
            int col = nt * 8 + 2 * (lane & 3);
            *(float2*)&scratch[mt * 1024 + row_r * 64 + col] =
                make_float2(o[nt][0], o[nt][1]);
            *(float2*)&scratch[mt * 1024 + (row_r + 8) * 64 + col] =
                make_float2(o[nt][2], o[nt][3]);
        }
    }
    __syncthreads();
    if (half == 0) {
        int r1g = q0 + mt * 16 + row_r;
        int r2g = r1g + 8;
        #pragma unroll
        for (int nt = 0; nt < 8; nt++) {
            int col = nt * 8 + 2 * (lane & 3);
            float2 s1v = *(float2*)&scratch[mt * 1024 + row_r * 64 + col];
            float2 s2v = *(float2*)&scratch[mt * 1024 + (row_r + 8) * 64 + col];
            float w10 = (o[nt][0] + s1v.x) * inv1, w11 = (o[nt][1] + s1v.y) * inv1;
            float w20 = (o[nt][2] + s2v.x) * inv2, w21 = (o[nt][3] + s2v.y) * inv2;
            *(uint32_t*)(ao + ((size_t)bb * T + r1g) * DIM + h * 64 + col) = pkh(w10, w11);
            *(uint32_t*)(ao + ((size_t)bb * T + r2g) * DIM + h * 64 + col) = pkh(w20, w21);
        }
    }
}

// ---------------------------------------------------------------------------
extern "C" void kernel_launch(void* const* d_in, const int* in_sizes, int n_in,
                              void* d_out, int out_size)
{
    const float* x    = (const float*)d_in[0];
    const float* rope = (const float*)d_in[2];
    const float* Wq   = (const float*)d_in[3];
    const float* Wk   = (const float*)d_in[4];
    const float* Wv   = (const float*)d_in[5];
    const float* Wo   = (const float*)d_in[6];
    float* out = (float*)d_out;

    __half *xh, *whi, *wlo, *qh, *khi, *klo, *vh, *aoh;
    cudaGetSymbolAddress((void**)&xh,  g_xh);
    cudaGetSymbolAddress((void**)&whi, g_whi);
    cudaGetSymbolAddress((void**)&wlo, g_wlo);
    cudaGetSymbolAddress((void**)&qh,  g_qh);
    cudaGetSymbolAddress((void**)&khi, g_khi);
    cudaGetSymbolAddress((void**)&klo, g_klo);
    cudaGetSymbolAddress((void**)&vh,  g_vh);
    cudaGetSymbolAddress((void**)&aoh, g_aoh);

    cudaFuncSetAttribute(gemm_hmma, cudaFuncAttributeMaxDynamicSharedMemorySize, GEMM_SMEM);
    cudaFuncSetAttribute(attn_hmma, cudaFuncAttributeMaxDynamicSharedMemorySize, ATT_SMEM);

    const int xn4 = XSZ / 4;
    const int wn4tot = 4 * WSZ / 4;

    tohalf<<<xn4 / 256, 256>>>(x, xh, xn4);
    split_w4<<<wn4tot / 256, 256>>>(Wq, Wk, Wv, Wo, whi, wlo);

    // fused QKV (N = 3072)
    gemm_hmma<<<dim3(24, 32), 256, GEMM_SMEM>>>(xh, whi, wlo,
                                                nullptr, qh, khi, klo, vh, 1);

    // RoPE once per element, in-place (scale folded into Q)
    int nrope = B * H * T * 32;
    rope_prep<<<(nrope + 255) / 256, 256>>>(qh, khi, klo, rope);

    attn_hmma<<<dim3(T / 64, H, B), 256, ATT_SMEM>>>(qh, khi, klo, vh, aoh);

    // O projection (W index 3)
    gemm_hmma<<<dim3(8, 32), 256, GEMM_SMEM>>>(aoh, whi + 3*(size_t)WSZ, wlo + 3*(size_t)WSZ,
                                               out, nullptr, nullptr, nullptr, nullptr, 0);
}

// round 9
// speedup vs baseline: 2.3033x; 1.0861x over previous
#include <cuda_runtime.h>
#include <cuda_fp16.h>
#include <math.h>
#include <stdint.h>

#define B 2
#define T 2048
#define H 16
#define DH 64
#define DIM 1024
#define M_TOTAL (B*T)      // 4096
#define SZH (B*H*T*DH)     // 4194304
#define XSZ (M_TOTAL*DIM)  // 4194304
#define WSZ (DIM*DIM)      // 1048576
#define ATT_SCALE 0.125f

// ---------------- scratch (device globals; allocation-free) ----------------
__device__ __half g_xh [XSZ];
__device__ __half g_whi[4*WSZ];
__device__ __half g_wlo[4*WSZ];
__device__ __half g_qh [SZH];
__device__ __half g_khi[SZH];
__device__ __half g_klo[SZH];
__device__ __half g_vh [SZH];
__device__ __half g_aoh[XSZ];

// ---------------- helpers ----------------
__device__ __forceinline__ uint32_t smem_u32(const void* p) {
    uint32_t a;
    asm("{ .reg .u64 t; cvta.to.shared.u64 t, %1; cvt.u32.u64 %0, t; }"
        : "=r"(a) : "l"(p));
    return a;
}

#define CP_ASYNC16(dst_u32, src_ptr) \
    asm volatile("cp.async.cg.shared.global [%0], [%1], 16;" :: "r"(dst_u32), "l"(src_ptr))
#define CP_COMMIT()  asm volatile("cp.async.commit_group;" ::: "memory")
#define CP_WAIT0()   asm volatile("cp.async.wait_group 0;" ::: "memory")
#define CP_WAIT1()   asm volatile("cp.async.wait_group 1;" ::: "memory")

#define LDM_X4(r0,r1,r2,r3, addr) \
    asm volatile("ldmatrix.sync.aligned.m8n8.x4.shared.b16 {%0,%1,%2,%3}, [%4];" \
                 : "=r"(r0), "=r"(r1), "=r"(r2), "=r"(r3) : "r"(addr))
#define LDM_X4_T(r0,r1,r2,r3, addr) \
    asm volatile("ldmatrix.sync.aligned.m8n8.x4.trans.shared.b16 {%0,%1,%2,%3}, [%4];" \
                 : "=r"(r0), "=r"(r1), "=r"(r2), "=r"(r3) : "r"(addr))

__device__ __forceinline__ void mma_f16(float* c, const uint32_t* a, const uint32_t* b) {
    asm volatile(
        "mma.sync.aligned.m16n8k16.row.col.f32.f16.f16.f32 "
        "{%0,%1,%2,%3}, {%4,%5,%6,%7}, {%8,%9}, {%0,%1,%2,%3};"
        : "+f"(c[0]), "+f"(c[1]), "+f"(c[2]), "+f"(c[3])
        : "r"(a[0]), "r"(a[1]), "r"(a[2]), "r"(a[3]), "r"(b[0]), "r"(b[1]));
}

__device__ __forceinline__ uint32_t pkh(float a, float b) {
    __half2 t = __floats2half2_rn(a, b);
    return *(uint32_t*)&t;
}

// ---------------------------------------------------------------------------
// fp32 -> fp16 (single)
// ---------------------------------------------------------------------------
__global__ void tohalf(const float* __restrict__ x, __half* __restrict__ o, int n4)
{
    int i = blockIdx.x * blockDim.x + threadIdx.x;
    if (i >= n4) return;
    float4 v = ((const float4*)x)[i];
    uint2 u;
    u.x = pkh(v.x, v.y);
    u.y = pkh(v.z, v.w);
    *(uint2*)(o + 4 * (size_t)i) = u;
}

// ---------------------------------------------------------------------------
// 4 weight matrices -> fp16 hi (+lo only where consumed: Wk, Wo)
// ---------------------------------------------------------------------------
__global__ void split_w4(const float* __restrict__ W0, const float* __restrict__ W1,
                         const float* __restrict__ W2, const float* __restrict__ W3,
                         __half* __restrict__ hi, __half* __restrict__ lo)
{
    int i = blockIdx.x * blockDim.x + threadIdx.x;  // over 4*WSZ/4
    int which = i >> 18;                            // WSZ/4 = 2^18
    int j = i & 0x3FFFF;
    const float* W = (which == 0) ? W0 : (which == 1) ? W1 : (which == 2) ? W2 : W3;
    float4 v = ((const float4*)W)[j];
    float f[4] = {v.x, v.y, v.z, v.w};
    float r[4];
    __half h[4];
    #pragma unroll
    for (int e = 0; e < 4; e++) {
        h[e] = __float2half_rn(f[e]);
        r[e] = f[e] - __half2float(h[e]);
    }
    size_t base = (size_t)which * WSZ + (size_t)j * 4;
    uint2 uh;
    uh.x = pkh(__half2float(h[0]), __half2float(h[1]));
    uh.y = pkh(__half2float(h[2]), __half2float(h[3]));
    *(uint2*)(hi + base) = uh;
    if (which == 1 || which == 3) {     // only K and O weights need lo
        uint2 ul;
        ul.x = pkh(r[0], r[1]);
        ul.y = pkh(r[2], r[3]);
        *(uint2*)(lo + base) = ul;
    }
}

// ---------------------------------------------------------------------------
// RoPE prep (IN-PLACE, vectorized): ropes Q (folds ATT_SCALE) and K (hi/lo).
// Thread owns 8 consecutive (d, d+32) pairs of one (b,h,t) row.
// ---------------------------------------------------------------------------
__global__ void rope_prep(__half* __restrict__ q,
                          __half* __restrict__ khi, __half* __restrict__ klo,
                          const float* __restrict__ rope)
{
    int idx = blockIdx.x * blockDim.x + threadIdx.x;   // B*H*T*4
    if (idx >= B * H * T * 4) return;
    int d8   = (idx & 3) * 8;          // 0,8,16,24
    int rest = idx >> 2;               // (b*H+h)*T + t
    int t    = rest & (T - 1);
    int bh   = rest >> 11;
    int bidx = bh >> 4;

    const float* pr = rope + ((size_t)bidx * T + t) * DH + d8;
    float p1[8], p2[8];
    *(float4*)(p1)     = *(const float4*)(pr);
    *(float4*)(p1 + 4) = *(const float4*)(pr + 4);
    *(float4*)(p2)     = *(const float4*)(pr + 32);
    *(float4*)(p2 + 4) = *(const float4*)(pr + 36);

    float c1[8], s1[8], c2[8], s2[8];
    #pragma unroll
    for (int e = 0; e < 8; e++) {
        __sincosf(p1[e], &s1[e], &c1[e]);
        __sincosf(p2[e], &s2[e], &c2[e]);
    }

    size_t base = (size_t)rest * DH + d8;

    // ---- Q (scale folded) ----
    {
        uint4 ua = *(uint4*)(q + base);
        uint4 ub = *(uint4*)(q + base + 32);
        __half* ha = (__half*)&ua;
        __half* hb = (__half*)&ub;
        uint4 oa, ob;
        __half* oa_h = (__half*)&oa;
        __half* ob_h = (__half*)&ob;
        #pragma unroll
        for (int e = 0; e < 8; e++) {
            float x1 = __half2float(ha[e]);
            float x2 = __half2float(hb[e]);
            oa_h[e] = __float2half_rn((x1 * c1[e] - x2 * s1[e]) * ATT_SCALE);
            ob_h[e] = __float2half_rn((x2 * c2[e] + x1 * s2[e]) * ATT_SCALE);
        }
        *(uint4*)(q + base)      = oa;
        *(uint4*)(q + base + 32) = ob;
    }
    // ---- K (reconstruct, rope, re-split) ----
    {
        uint4 uha = *(uint4*)(khi + base);
        uint4 uhb = *(uint4*)(khi + base + 32);
        uint4 ula = *(uint4*)(klo + base);
        uint4 ulb = *(uint4*)(klo + base + 32);
        __half* hha = (__half*)&uha; __half* hhb = (__half*)&uhb;
        __half* hla = (__half*)&ula; __half* hlb = (__half*)&ulb;
        uint4 oha, ohb, ola, olb;
        __half* poha = (__half*)&oha; __half* pohb = (__half*)&ohb;
        __half* pola = (__half*)&ola; __half* polb = (__half*)&olb;
        #pragma unroll
        for (int e = 0; e < 8; e++) {
            float k1 = __half2float(hha[e]) + __half2float(hla[e]);
            float k2 = __half2float(hhb[e]) + __half2float(hlb[e]);
            float y1 = k1 * c1[e] - k2 * s1[e];
            float y2 = k2 * c2[e] + k1 * s2[e];
            __half h1 = __float2half_rn(y1), h2 = __float2half_rn(y2);
            poha[e] = h1; pola[e] = __float2half_rn(y1 - __half2float(h1));
            pohb[e] = h2; polb[e] = __float2half_rn(y2 - __half2float(h2));
        }
        *(uint4*)(khi + base)      = oha;
        *(uint4*)(khi + base + 32) = ohb;
        *(uint4*)(klo + base)      = ola;
        *(uint4*)(klo + base + 32) = olb;
    }
}

// ---------------------------------------------------------------------------
// Tensor-core GEMM: C[m,n] = sum_k A[m,k]*W[n,k]
// A single fp16; W hi (+lo 2nd pass only where needed).
// mode 0: Cf fp32 row-major (O proj, 2-pass)
// mode 1: QKV fused (grid.x=24): which=n0>>10; lo-pass only for K (which==1)
// ---------------------------------------------------------------------------
#define BKC 32
#define RS  40
#define TILE_B (128*RS*2)          // 10240 bytes
#define STG (3*TILE_B)             // A, Wh, Wl
#define GEMM_SMEM (2*STG)          // 61440

__global__ __launch_bounds__(256) void gemm_hmma(
    const __half* __restrict__ A,
    const __half* __restrict__ Wh, const __half* __restrict__ Wl,
    float* __restrict__ Cf,
    __half* __restrict__ Cq, __half* __restrict__ Ckh,
    __half* __restrict__ Ckl, __half* __restrict__ Cv,
    int mode)
{
    extern __shared__ __align__(16) char sm[];
    const uint32_t smb = smem_u32(sm);

    const int tid  = threadIdx.x;
    const int m0   = blockIdx.y * 128;
    const int n0   = blockIdx.x * 128;
    const int wid  = tid >> 5;
    const int lane = tid & 31;
    const int g    = lane >> 2;
    const int t2   = (lane & 3) * 2;
    const int wm   = (wid & 1) * 64;
    const int wn   = (wid >> 1) * 32;

    const int which = (mode == 1) ? (n0 >> 10) : 3;
    const bool use_lo = (mode == 0) || (which == 1);

    float acc[4][4][4];
    #pragma unroll
    for (int mt = 0; mt < 4; mt++)
        #pragma unroll
        for (int nt = 0; nt < 4; nt++)
            #pragma unroll
            for (int e = 0; e < 4; e++) acc[mt][nt][e] = 0.f;

    auto load_chunk = [&](int c, int buf) {
        const int k0 = c * BKC;
        const uint32_t bb = smb + (uint32_t)buf * STG;
        #pragma unroll
        for (int i = 0; i < 6; i++) {
            int idx = tid + i * 256;      // 0..1535
            int arr = idx / 512;
            int rem = idx & 511;
            int r   = rem >> 2;
            int c8  = (rem & 3) * 8;
            const __half* src;
            int rowbase;
            if (arr == 0)      { src = A;  rowbase = m0 + r; }
            else if (arr == 1) { src = Wh; rowbase = n0 + r; }
            else               { if (!use_lo) continue; src = Wl; rowbase = n0 + r; }
            uint32_t dst = bb + (uint32_t)arr * TILE_B + (uint32_t)(r * RS + c8) * 2;
            CP_ASYNC16(dst, src + (size_t)rowbase * DIM + k0 + c8);
        }
    };

    const uint32_t a_off = (uint32_t)((wm + (lane & 15)) * RS + ((lane & 16) ? 8 : 0));
    const uint32_t b_off = (uint32_t)((wn + (lane & 7) + ((lane & 16) ? 8 : 0)) * RS
                                      + ((lane & 8) ? 8 : 0));

    const int NC = DIM / BKC;   // 32
    load_chunk(0, 0);
    CP_COMMIT();

    for (int c = 0; c < NC; c++) {
        if (c + 1 < NC) {
            load_chunk(c + 1, (c + 1) & 1);
            CP_COMMIT();
            CP_WAIT1();
        } else {
            CP_WAIT0();
        }
        __syncthreads();

        const uint32_t base = smb + (uint32_t)(c & 1) * STG;

        #pragma unroll
        for (int ks = 0; ks < 2; ks++) {
            const uint32_t kc = (uint32_t)(ks * 16);
            uint32_t ar[4][4], wh[2][4], wl[2][4];
            #pragma unroll
            for (int mt = 0; mt < 4; mt++) {
                uint32_t addr = base + (a_off + (uint32_t)(mt * 16) * RS + kc) * 2;
                LDM_X4(ar[mt][0], ar[mt][1], ar[mt][2], ar[mt][3], addr);
            }
            #pragma unroll
            for (int p = 0; p < 2; p++) {
                uint32_t addr = base + TILE_B + (b_off + (uint32_t)(p * 16) * RS + kc) * 2;
                LDM_X4(wh[p][0], wh[p][1], wh[p][2], wh[p][3], addr);
                if (use_lo) {
                    LDM_X4(wl[p][0], wl[p][1], wl[p][2], wl[p][3], addr + TILE_B);
                }
            }
            #pragma unroll
            for (int mt = 0; mt < 4; mt++)
                #pragma unroll
                for (int nt = 0; nt < 4; nt++) {
                    uint32_t bh[2] = { wh[nt>>1][(nt&1)*2], wh[nt>>1][(nt&1)*2+1] };
                    mma_f16(acc[mt][nt], ar[mt], bh);
                    if (use_lo) {
                        uint32_t bl[2] = { wl[nt>>1][(nt&1)*2], wl[nt>>1][(nt&1)*2+1] };
                        mma_f16(acc[mt][nt], ar[mt], bl);
                    }
                }
        }
        __syncthreads();
    }

    // ---- epilogue ----
    if (mode == 0) {
        #pragma unroll
        for (int mt = 0; mt < 4; mt++) {
            int row0 = m0 + wm + mt * 16 + g;
            #pragma unroll
            for (int nt = 0; nt < 4; nt++) {
                int col = n0 + wn + nt * 8 + t2;
                *(float2*)(Cf + (size_t)row0 * DIM + col) =
                    make_float2(acc[mt][nt][0], acc[mt][nt][1]);
                *(float2*)(Cf + (size_t)(row0 + 8) * DIM + col) =
                    make_float2(acc[mt][nt][2], acc[mt][nt][3]);
            }
        }
    } else {
        int n0w = n0 & 1023;
        #pragma unroll
        for (int mt = 0; mt < 4; mt++) {
            int row0 = m0 + wm + mt * 16 + g;
            int bb0 = row0 >> 11, t0 = row0 & (T - 1);
            int bb1 = (row0 + 8) >> 11, t1 = (row0 + 8) & (T - 1);
            #pragma unroll
            for (int nt = 0; nt < 4; nt++) {
                int col = n0w + wn + nt * 8 + t2;
                int h = col >> 6, d = col & 63;
                size_t i0 = (((size_t)bb0 * H + h) * T + t0) * DH + d;
                size_t i1 = (((size_t)bb1 * H + h) * T + t1) * DH + d;
                float a0 = acc[mt][nt][0], a1 = acc[mt][nt][1];
                float a2 = acc[mt][nt][2], a3 = acc[mt][nt][3];
                if (which == 0) {
                    *(uint32_t*)(Cq + i0) = pkh(a0, a1);
                    *(uint32_t*)(Cq + i1) = pkh(a2, a3);
                } else if (which == 2) {
                    *(uint32_t*)(Cv + i0) = pkh(a0, a1);
                    *(uint32_t*)(Cv + i1) = pkh(a2, a3);
                } else {
                    __half h0 = __float2half_rn(a0), h1 = __float2half_rn(a1);
                    __half h2 = __float2half_rn(a2), h3 = __float2half_rn(a3);
                    *(uint32_t*)(Ckh + i0) = pkh(__half2float(h0), __half2float(h1));
                    *(uint32_t*)(Ckh + i1) = pkh(__half2float(h2), __half2float(h3));
                    *(uint32_t*)(Ckl + i0) = pkh(a0 - __half2float(h0), a1 - __half2float(h1));
                    *(uint32_t*)(Ckl + i1) = pkh(a2 - __half2float(h2), a3 - __half2float(h3));
                }
            }
        }
    }
}

// ---------------------------------------------------------------------------
// Tensor-core sliding-window attention. Pre-roped inputs; load = pure cp.async.
// Block = (64 queries, h, b); keys [q0-128, q0+63] -> 192.
// S = Q*Kh + Q*Kl (2-pass); PV = P*V (1-pass). ao written as fp16.
// ---------------------------------------------------------------------------
#define ARS 72
#define AQ  0
#define AKH (64*ARS*2)               // 9216
#define AKL (AKH + 192*ARS*2)        // 36864
#define AV  (AKL + 192*ARS*2)        // 64512
#define ARED (AV + 192*ARS*2)        // 92160
#define ATT_SMEM (ARED + 1024)       // 93184

__global__ __launch_bounds__(256, 2) void attn_hmma(
    const __half* __restrict__ qh,
    const __half* __restrict__ khi, const __half* __restrict__ klo,
    const __half* __restrict__ vh,
    __half* __restrict__ ao)
{
    extern __shared__ __align__(16) char sm[];
    const uint32_t smb = smem_u32(sm);
    float* redm = (float*)(sm + ARED);
    float* reds = (float*)(sm + ARED + 512);
    float* scratch = (float*)sm;    // 16KB, reused post-S-phase

    const int q0 = blockIdx.x * 64;
    const int h  = blockIdx.y;
    const int bb = blockIdx.z;
    const int tid = threadIdx.x;
    const int wid = tid >> 5;
    const int lane = tid & 31;
    const size_t headbase = ((size_t)bb * H + h) * T * DH;
    const int k0 = q0 - 128;

    // ---- load: pure cp.async ----
    for (int i = tid; i < 512; i += 256) {
        int r = i >> 3, s = i & 7;
        CP_ASYNC16(smb + AQ + (uint32_t)(r * ARS + s * 8) * 2,
                   qh + headbase + (size_t)(q0 + r) * DH + s * 8);
    }
    for (int i = tid; i < 1536; i += 256) {
        int r = i >> 3, s = i & 7;
        int kg = k0 + r;
        int kc = kg < 0 ? 0 : (kg >= T ? T - 1 : kg);
        size_t src = headbase + (size_t)kc * DH + s * 8;
        uint32_t off = (uint32_t)(r * ARS + s * 8) * 2;
        CP_ASYNC16(smb + AKH + off, khi + src);
        CP_ASYNC16(smb + AKL + off, klo + src);
        CP_ASYNC16(smb + AV  + off, vh  + src);
    }
    CP_COMMIT();
    CP_WAIT0();
    __syncthreads();

    const int mt   = wid & 3;
    const int half = wid >> 2;
    const int row_r = lane >> 2;

    // ---- S = Q K^T (2-pass: Kh then Kl) ----
    float p[12][4];
    #pragma unroll
    for (int nt = 0; nt < 12; nt++)
        #pragma unroll
        for (int e = 0; e < 4; e++) p[nt][e] = 0.f;

    const uint32_t qa_off = (uint32_t)((mt * 16 + (lane & 15)) * ARS
                                       + ((lane & 16) ? 8 : 0)) * 2;
    const uint32_t kb_row = (uint32_t)(half * 96 + (lane & 7) + ((lane & 16) ? 8 : 0));
    const uint32_t kb_coff = (uint32_t)((lane & 8) ? 8 : 0);

    #pragma unroll
    for (int kt = 0; kt < 4; kt++) {
        const uint32_t kc = (uint32_t)(kt * 16);
        uint32_t aq[4];
        LDM_X4(aq[0], aq[1], aq[2], aq[3], smb + AQ + qa_off + kc * 2);
        #pragma unroll
        for (int pp = 0; pp < 6; pp++) {
            uint32_t addr = smb + AKH
                + ((kb_row + (uint32_t)(pp * 16)) * ARS + kc + kb_coff) * 2;
            uint32_t bh[4], bl[4];
            LDM_X4(bh[0], bh[1], bh[2], bh[3], addr);
            LDM_X4(bl[0], bl[1], bl[2], bl[3], addr + (AKL - AKH));
            #pragma unroll
            for (int sub = 0; sub < 2; sub++) {
                int nt = pp * 2 + sub;
                uint32_t bbh[2] = { bh[sub*2], bh[sub*2+1] };
                uint32_t bbl[2] = { bl[sub*2], bl[sub*2+1] };
                mma_f16(p[nt], aq, bbh);
                mma_f16(p[nt], aq, bbl);
            }
        }
    }

    // ---- mask (scale folded into Q at prep) ----
    {
        int qg1 = q0 + mt * 16 + row_r;
        int qg2 = qg1 + 8;
        #pragma unroll
        for (int nt = 0; nt < 12; nt++) {
            int cb = k0 + half * 96 + nt * 8 + 2 * (lane & 3);
            #pragma unroll
            for (int e = 0; e < 4; e++) {
                int kg = cb + (e & 1);
                int qg = (e & 2) ? qg2 : qg1;
                bool valid = (kg >= 0) && (kg <= qg) && (kg >= qg - 128);
                if (!valid) p[nt][e] = -1e30f;
            }
        }
    }

    // ---- softmax (cross-half via smem) ----
    float inv1, inv2;
    {
        float m0v = -1e30f, m1v = -1e30f;
        #pragma unroll
        for (int nt = 0; nt < 12; nt++) {
            m0v = fmaxf(m0v, fmaxf(p[nt][0], p[nt][1]));
            m1v = fmaxf(m1v, fmaxf(p[nt][2], p[nt][3]));
        }
        m0v = fmaxf(m0v, __shfl_xor_sync(0xffffffffu, m0v, 1));
        m0v = fmaxf(m0v, __shfl_xor_sync(0xffffffffu, m0v, 2));
        m1v = fmaxf(m1v, __shfl_xor_sync(0xffffffffu, m1v, 1));
        m1v = fmaxf(m1v, __shfl_xor_sync(0xffffffffu, m1v, 2));
        if ((lane & 3) == 0) {
            redm[half * 64 + mt * 16 + row_r]     = m0v;
            redm[half * 64 + mt * 16 + row_r + 8] = m1v;
        }
        __syncthreads();
        float M0 = fmaxf(redm[mt*16 + row_r],     redm[64 + mt*16 + row_r]);
        float M1 = fmaxf(redm[mt*16 + row_r + 8], redm[64 + mt*16 + row_r + 8]);

        float s0 = 0.f, s1 = 0.f;
        #pragma unroll
        for (int nt = 0; nt < 12; nt++) {
            p[nt][0] = __expf(p[nt][0] - M0); s0 += p[nt][0];
            p[nt][1] = __expf(p[nt][1] - M0); s0 += p[nt][1];
            p[nt][2] = __expf(p[nt][2] - M1); s1 += p[nt][2];
            p[nt][3] = __expf(p[nt][3] - M1); s1 += p[nt][3];
        }
        s0 += __shfl_xor_sync(0xffffffffu, s0, 1);
        s0 += __shfl_xor_sync(0xffffffffu, s0, 2);
        s1 += __shfl_xor_sync(0xffffffffu, s1, 1);
        s1 += __shfl_xor_sync(0xffffffffu, s1, 2);
        if ((lane & 3) == 0) {
            reds[half * 64 + mt * 16 + row_r]     = s0;
            reds[half * 64 + mt * 16 + row_r + 8] = s1;
        }
        __syncthreads();
        inv1 = 1.0f / (reds[mt*16 + row_r]     + reds[64 + mt*16 + row_r]);
        inv2 = 1.0f / (reds[mt*16 + row_r + 8] + reds[64 + mt*16 + row_r + 8]);
    }

    // ---- O = P V (single pass, ldmatrix.trans on V) ----
    float o[8][4];
    #pragma unroll
    for (int nt = 0; nt < 8; nt++)
        #pragma unroll
        for (int e = 0; e < 4; e++) o[nt][e] = 0.f;

    const uint32_t vb_row = (uint32_t)(half * 96 + (lane & 7) + ((lane & 8) ? 8 : 0));
    const uint32_t vb_coff = (uint32_t)((lane & 16) ? 8 : 0);

    #pragma unroll
    for (int kt = 0; kt < 6; kt++) {
        uint32_t pa[4];
        {
            float* e0 = p[2*kt]; float* e1 = p[2*kt+1];
            pa[0] = pkh(e0[0], e0[1]);
            pa[1] = pkh(e0[2], e0[3]);
            pa[2] = pkh(e1[0], e1[1]);
            pa[3] = pkh(e1[2], e1[3]);
        }
        #pragma unroll
        for (int dp = 0; dp < 4; dp++) {
            uint32_t addr = smb + AV
                + ((vb_row + (uint32_t)(kt * 16)) * ARS + (uint32_t)(dp * 16) + vb_coff) * 2;
            uint32_t vv[4];
            LDM_X4_T(vv[0], vv[1], vv[2], vv[3], addr);
            #pragma unroll
            for (int sub = 0; sub < 2; sub++) {
                int nt = dp * 2 + sub;
                uint32_t bb2[2] = { vv[sub*2], vv[sub*2+1] };
                mma_f16(o[nt], pa, bb2);
            }
        }
    }

    // ---- combine halves, write ao as fp16 ----
    if (half == 1) {
        #pragma unroll
        for (int nt = 0; nt < 8; nt++) {
            int col = nt * 8 + 2 * (lane & 3);
            *(float2*)&scratch[mt * 1024 + row_r * 64 + col] =
                make_float2(o[nt][0], o[nt][1]);
            *(float2*)&scratch[mt * 1024 + (row_r + 8) * 64 + col] =
                make_float2(o[nt][2], o[nt][3]);
        }
    }
    __syncthreads();
    if (half == 0) {
        int r1g = q0 + mt * 16 + row_r;
        int r2g = r1g + 8;
        #pragma unroll
        for (int nt = 0; nt < 8; nt++) {
            int col = nt * 8 + 2 * (lane & 3);
            float2 s1v = *(float2*)&scratch[mt * 1024 + row_r * 64 + col];
            float2 s2v = *(float2*)&scratch[mt * 1024 + (row_r + 8) * 64 + col];
            float w10 = (o[nt][0] + s1v.x) * inv1, w11 = (o[nt][1] + s1v.y) * inv1;
            float w20 = (o[nt][2] + s2v.x) * inv2, w21 = (o[nt][3] + s2v.y) * inv2;
            *(uint32_t*)(ao + ((size_t)bb * T + r1g) * DIM + h * 64 + col) = pkh(w10, w11);
            *(uint32_t*)(ao + ((size_t)bb * T + r2g) * DIM + h * 64 + col) = pkh(w20, w21);
        }
    }
}

// ---------------------------------------------------------------------------
extern "C" void kernel_launch(void* const* d_in, const int* in_sizes, int n_in,
                              void* d_out, int out_size)
{
    const float* x    = (const float*)d_in[0];
    const float* rope = (const float*)d_in[2];
    const float* Wq   = (const float*)d_in[3];
    const float* Wk   = (const float*)d_in[4];
    const float* Wv   = (const float*)d_in[5];
    const float* Wo   = (const float*)d_in[6];
    float* out = (float*)d_out;

    __half *xh, *whi, *wlo, *qh, *khi, *klo, *vh, *aoh;
    cudaGetSymbolAddress((void**)&xh,  g_xh);
    cudaGetSymbolAddress((void**)&whi, g_whi);
    cudaGetSymbolAddress((void**)&wlo, g_wlo);
    cudaGetSymbolAddress((void**)&qh,  g_qh);
    cudaGetSymbolAddress((void**)&khi, g_khi);
    cudaGetSymbolAddress((void**)&klo, g_klo);
    cudaGetSymbolAddress((void**)&vh,  g_vh);
    cudaGetSymbolAddress((void**)&aoh, g_aoh);

    cudaFuncSetAttribute(gemm_hmma, cudaFuncAttributeMaxDynamicSharedMemorySize, GEMM_SMEM);
    cudaFuncSetAttribute(attn_hmma, cudaFuncAttributeMaxDynamicSharedMemorySize, ATT_SMEM);

    const int xn4 = XSZ / 4;
    const int wn4tot = 4 * WSZ / 4;

    tohalf<<<xn4 / 256, 256>>>(x, xh, xn4);
    split_w4<<<wn4tot / 256, 256>>>(Wq, Wk, Wv, Wo, whi, wlo);

    // fused QKV (N = 3072); lo-pass only on K-third
    gemm_hmma<<<dim3(24, 32), 256, GEMM_SMEM>>>(xh, whi, wlo,
                                                nullptr, qh, khi, klo, vh, 1);

    // RoPE once per element, in-place (scale folded into Q)
    int nrope = B * H * T * 4;
    rope_prep<<<(nrope + 255) / 256, 256>>>(qh, khi, klo, rope);

    attn_hmma<<<dim3(T / 64, H, B), 256, ATT_SMEM>>>(qh, khi, klo, vh, aoh);

    // O projection (W index 3, 2-pass)
    gemm_hmma<<<dim3(8, 32), 256, GEMM_SMEM>>>(aoh, whi + 3*(size_t)WSZ, wlo + 3*(size_t)WSZ,
                                               out, nullptr, nullptr, nullptr, nullptr, 0);
}

// round 11
// speedup vs baseline: 2.3235x; 1.0087x over previous
#include <cuda_runtime.h>
#include <cuda_fp16.h>
#include <math.h>
#include <stdint.h>

#define B 2
#define T 2048
#define H 16
#define DH 64
#define DIM 1024
#define M_TOTAL (B*T)      // 4096
#define SZH (B*H*T*DH)     // 4194304
#define XSZ (M_TOTAL*DIM)  // 4194304
#define WSZ (DIM*DIM)      // 1048576
#define ATT_SCALE 0.125f

// ---------------- scratch (device globals; allocation-free) ----------------
__device__ __half g_xh [XSZ];
__device__ __half g_whi[4*WSZ];
__device__ __half g_wlo[WSZ];      // only Wo needs a lo part
__device__ __half g_qh [SZH];
__device__ __half g_kh [SZH];
__device__ __half g_vh [SZH];
__device__ __half g_aoh[XSZ];

// ---------------- helpers ----------------
__device__ __forceinline__ uint32_t smem_u32(const void* p) {
    uint32_t a;
    asm("{ .reg .u64 t; cvta.to.shared.u64 t, %1; cvt.u32.u64 %0, t; }"
        : "=r"(a) : "l"(p));
    return a;
}

#define CP_ASYNC16(dst_u32, src_ptr) \
    asm volatile("cp.async.cg.shared.global [%0], [%1], 16;" :: "r"(dst_u32), "l"(src_ptr))
#define CP_COMMIT()  asm volatile("cp.async.commit_group;" ::: "memory")
#define CP_WAIT0()   asm volatile("cp.async.wait_group 0;" ::: "memory")
#define CP_WAIT1()   asm volatile("cp.async.wait_group 1;" ::: "memory")

#define LDM_X4(r0,r1,r2,r3, addr) \
    asm volatile("ldmatrix.sync.aligned.m8n8.x4.shared.b16 {%0,%1,%2,%3}, [%4];" \
                 : "=r"(r0), "=r"(r1), "=r"(r2), "=r"(r3) : "r"(addr))
#define LDM_X4_T(r0,r1,r2,r3, addr) \
    asm volatile("ldmatrix.sync.aligned.m8n8.x4.trans.shared.b16 {%0,%1,%2,%3}, [%4];" \
                 : "=r"(r0), "=r"(r1), "=r"(r2), "=r"(r3) : "r"(addr))

__device__ __forceinline__ void mma_f16(float* c, const uint32_t* a, const uint32_t* b) {
    asm volatile(
        "mma.sync.aligned.m16n8k16.row.col.f32.f16.f16.f32 "
        "{%0,%1,%2,%3}, {%4,%5,%6,%7}, {%8,%9}, {%0,%1,%2,%3};"
        : "+f"(c[0]), "+f"(c[1]), "+f"(c[2]), "+f"(c[3])
        : "r"(a[0]), "r"(a[1]), "r"(a[2]), "r"(a[3]), "r"(b[0]), "r"(b[1]));
}

__device__ __forceinline__ uint32_t pkh(float a, float b) {
    __half2 t = __floats2half2_rn(a, b);
    return *(uint32_t*)&t;
}

// ---------------------------------------------------------------------------
// fp32 -> fp16 (single)
// ---------------------------------------------------------------------------
__global__ void tohalf(const float* __restrict__ x, __half* __restrict__ o, int n4)
{
    int i = blockIdx.x * blockDim.x + threadIdx.x;
    if (i >= n4) return;
    float4 v = ((const float4*)x)[i];
    uint2 u;
    u.x = pkh(v.x, v.y);
    u.y = pkh(v.z, v.w);
    *(uint2*)(o + 4 * (size_t)i) = u;
}

// ---------------------------------------------------------------------------
// 4 weight matrices -> fp16 hi (+lo only for Wo)
// ---------------------------------------------------------------------------
__global__ void split_w4(const float* __restrict__ W0, const float* __restrict__ W1,
                         const float* __restrict__ W2, const float* __restrict__ W3,
                         __half* __restrict__ hi, __half* __restrict__ lo)
{
    int i = blockIdx.x * blockDim.x + threadIdx.x;  // over 4*WSZ/4
    int which = i >> 18;                            // WSZ/4 = 2^18
    int j = i & 0x3FFFF;
    const float* W = (which == 0) ? W0 : (which == 1) ? W1 : (which == 2) ? W2 : W3;
    float4 v = ((const float4*)W)[j];
    float f[4] = {v.x, v.y, v.z, v.w};
    __half h[4];
    #pragma unroll
    for (int e = 0; e < 4; e++) h[e] = __float2half_rn(f[e]);
    size_t base = (size_t)which * WSZ + (size_t)j * 4;
    uint2 uh;
    uh.x = pkh(__half2float(h[0]), __half2float(h[1]));
    uh.y = pkh(__half2float(h[2]), __half2float(h[3]));
    *(uint2*)(hi + base) = uh;
    if (which == 3) {                  // only O weights need lo
        uint2 ul;
        ul.x = pkh(f[0] - __half2float(h[0]), f[1] - __half2float(h[1]));
        ul.y = pkh(f[2] - __half2float(h[2]), f[3] - __half2float(h[3]));
        *(uint2*)(lo + (size_t)j * 4) = ul;
    }
}

// ---------------------------------------------------------------------------
// RoPE prep (IN-PLACE, vectorized): Q (folds ATT_SCALE) and K, both single fp16.
// Thread owns 8 consecutive (d, d+32) pairs of one (b,h,t) row.
// ---------------------------------------------------------------------------
__global__ void rope_prep(__half* __restrict__ q, __half* __restrict__ k,
                          const float* __restrict__ rope)
{
    int idx = blockIdx.x * blockDim.x + threadIdx.x;   // B*H*T*4
    if (idx >= B * H * T * 4) return;
    int d8   = (idx & 3) * 8;          // 0,8,16,24
    int rest = idx >> 2;               // (b*H+h)*T + t
    int t    = rest & (T - 1);
    int bh   = rest >> 11;
    int bidx = bh >> 4;

    const float* pr = rope + ((size_t)bidx * T + t) * DH + d8;
    float p1[8], p2[8];
    *(float4*)(p1)     = *(const float4*)(pr);
    *(float4*)(p1 + 4) = *(const float4*)(pr + 4);
    *(float4*)(p2)     = *(const float4*)(pr + 32);
    *(float4*)(p2 + 4) = *(const float4*)(pr + 36);

    float c1[8], s1[8], c2[8], s2[8];
    #pragma unroll
    for (int e = 0; e < 8; e++) {
        __sincosf(p1[e], &s1[e], &c1[e]);
        __sincosf(p2[e], &s2[e], &c2[e]);
    }

    size_t base = (size_t)rest * DH + d8;

    // ---- Q (scale folded) ----
    {
        uint4 ua = *(uint4*)(q + base);
        uint4 ub = *(uint4*)(q + base + 32);
        __half* ha = (__half*)&ua;
        __half* hb = (__half*)&ub;
        uint4 oa, ob;
        __half* oa_h = (__half*)&oa;
        __half* ob_h = (__half*)&ob;
        #pragma unroll
        for (int e = 0; e < 8; e++) {
            float x1 = __half2float(ha[e]);
            float x2 = __half2float(hb[e]);
            oa_h[e] = __float2half_rn((x1 * c1[e] - x2 * s1[e]) * ATT_SCALE);
            ob_h[e] = __float2half_rn((x2 * c2[e] + x1 * s2[e]) * ATT_SCALE);
        }
        *(uint4*)(q + base)      = oa;
        *(uint4*)(q + base + 32) = ob;
    }
    // ---- K (single fp16) ----
    {
        uint4 ua = *(uint4*)(k + base);
        uint4 ub = *(uint4*)(k + base + 32);
        __half* ha = (__half*)&ua;
        __half* hb = (__half*)&ub;
        uint4 oa, ob;
        __half* oa_h = (__half*)&oa;
        __half* ob_h = (__half*)&ob;
        #pragma unroll
        for (int e = 0; e < 8; e++) {
            float k1 = __half2float(ha[e]);
            float k2 = __half2float(hb[e]);
            oa_h[e] = __float2half_rn(k1 * c1[e] - k2 * s1[e]);
            ob_h[e] = __float2half_rn(k2 * c2[e] + k1 * s2[e]);
        }
        *(uint4*)(k + base)      = oa;
        *(uint4*)(k + base + 32) = ob;
    }
}

// ---------------------------------------------------------------------------
// Tensor-core GEMM: C[m,n] = sum_k A[m,k]*W[n,k]
// A single fp16; W hi (+lo 2nd pass only for O projection).
// mode 0: Cf fp32 row-major (O proj, 2-pass)
// mode 1: QKV fused (grid.x=24, all 1-pass): which=n0>>10 -> Cq/Ck/Cv fp16
// ---------------------------------------------------------------------------
#define BKC 32
#define RS  40
#define TILE_B (128*RS*2)          // 10240 bytes
#define STG (3*TILE_B)             // A, Wh, Wl
#define GEMM_SMEM (2*STG)          // 61440

__global__ __launch_bounds__(256) void gemm_hmma(
    const __half* __restrict__ A,
    const __half* __restrict__ Wh, const __half* __restrict__ Wl,
    float* __restrict__ Cf,
    __half* __restrict__ Cq, __half* __restrict__ Ck, __half* __restrict__ Cv,
    int mode)
{
    extern __shared__ __align__(16) char sm[];
    const uint32_t smb = smem_u32(sm);

    const int tid  = threadIdx.x;
    const int m0   = blockIdx.y * 128;
    const int n0   = blockIdx.x * 128;
    const int wid  = tid >> 5;
    const int lane = tid & 31;
    const int g    = lane >> 2;
    const int t2   = (lane & 3) * 2;
    const int wm   = (wid & 1) * 64;
    const int wn   = (wid >> 1) * 32;

    const int which = (mode == 1) ? (n0 >> 10) : 3;
    const bool use_lo = (mode == 0);

    float acc[4][4][4];
    #pragma unroll
    for (int mt = 0; mt < 4; mt++)
        #pragma unroll
        for (int nt = 0; nt < 4; nt++)
            #pragma unroll
            for (int e = 0; e < 4; e++) acc[mt][nt][e] = 0.f;

    auto load_chunk = [&](int c, int buf) {
        const int k0 = c * BKC;
        const uint32_t bb = smb + (uint32_t)buf * STG;
        #pragma unroll
        for (int i = 0; i < 6; i++) {
            int idx = tid + i * 256;      // 0..1535
            int arr = idx / 512;
            int rem = idx & 511;
            int r   = rem >> 2;
            int c8  = (rem & 3) * 8;
            const __half* src;
            int rowbase;
            if (arr == 0)      { src = A;  rowbase = m0 + r; }
            else if (arr == 1) { src = Wh; rowbase = n0 + r; }
            else               { if (!use_lo) continue; src = Wl; rowbase = n0 + r; }
            uint32_t dst = bb + (uint32_t)arr * TILE_B + (uint32_t)(r * RS + c8) * 2;
            CP_ASYNC16(dst, src + (size_t)rowbase * DIM + k0 + c8);
        }
    };

    const uint32_t a_off = (uint32_t)((wm + (lane & 15)) * RS + ((lane & 16) ? 8 : 0));
    const uint32_t b_off = (uint32_t)((wn + (lane & 7) + ((lane & 16) ? 8 : 0)) * RS
                                      + ((lane & 8) ? 8 : 0));

    const int NC = DIM / BKC;   // 32
    load_chunk(0, 0);
    CP_COMMIT();

    for (int c = 0; c < NC; c++) {
        if (c + 1 < NC) {
            load_chunk(c + 1, (c + 1) & 1);
            CP_COMMIT();
            CP_WAIT1();
        } else {
            CP_WAIT0();
        }
        __syncthreads();

        const uint32_t base = smb + (uint32_t)(c & 1) * STG;

        #pragma unroll
        for (int ks = 0; ks < 2; ks++) {
            const uint32_t kc = (uint32_t)(ks * 16);
            uint32_t ar[4][4], wh[2][4], wl[2][4];
            #pragma unroll
            for (int mt = 0; mt < 4; mt++) {
                uint32_t addr = base + (a_off + (uint32_t)(mt * 16) * RS + kc) * 2;
                LDM_X4(ar[mt][0], ar[mt][1], ar[mt][2], ar[mt][3], addr);
            }
            #pragma unroll
            for (int p = 0; p < 2; p++) {
                uint32_t addr = base + TILE_B + (b_off + (uint32_t)(p * 16) * RS + kc) * 2;
                LDM_X4(wh[p][0], wh[p][1], wh[p][2], wh[p][3], addr);
                if (use_lo) {
                    LDM_X4(wl[p][0], wl[p][1], wl[p][2], wl[p][3], addr + TILE_B);
                }
            }
            #pragma unroll
            for (int mt = 0; mt < 4; mt++)
                #pragma unroll
                for (int nt = 0; nt < 4; nt++) {
                    uint32_t bh[2] = { wh[nt>>1][(nt&1)*2], wh[nt>>1][(nt&1)*2+1] };
                    mma_f16(acc[mt][nt], ar[mt], bh);
                    if (use_lo) {
                        uint32_t bl[2] = { wl[nt>>1][(nt&1)*2], wl[nt>>1][(nt&1)*2+1] };
                        mma_f16(acc[mt][nt], ar[mt], bl);
                    }
                }
        }
        __syncthreads();
    }

    // ---- epilogue ----
    if (mode == 0) {
        #pragma unroll
        for (int mt = 0; mt < 4; mt++) {
            int row0 = m0 + wm + mt * 16 + g;
            #pragma unroll
            for (int nt = 0; nt < 4; nt++) {
                int col = n0 + wn + nt * 8 + t2;
                *(float2*)(Cf + (size_t)row0 * DIM + col) =
                    make_float2(acc[mt][nt][0], acc[mt][nt][1]);
                *(float2*)(Cf + (size_t)(row0 + 8) * DIM + col) =
                    make_float2(acc[mt][nt][2], acc[mt][nt][3]);
            }
        }
    } else {
        __half* C = (which == 0) ? Cq : (which == 1) ? Ck : Cv;
        int n0w = n0 & 1023;
        #pragma unroll
        for (int mt = 0; mt < 4; mt++) {
            int row0 = m0 + wm + mt * 16 + g;
            int bb0 = row0 >> 11, t0 = row0 & (T - 1);
            int bb1 = (row0 + 8) >> 11, t1 = (row0 + 8) & (T - 1);
            #pragma unroll
            for (int nt = 0; nt < 4; nt++) {
                int col = n0w + wn + nt * 8 + t2;
                int h = col >> 6, d = col & 63;
                size_t i0 = (((size_t)bb0 * H + h) * T + t0) * DH + d;
                size_t i1 = (((size_t)bb1 * H + h) * T + t1) * DH + d;
                *(uint32_t*)(C + i0) = pkh(acc[mt][nt][0], acc[mt][nt][1]);
                *(uint32_t*)(C + i1) = pkh(acc[mt][nt][2], acc[mt][nt][3]);
            }
        }
    }
}

// ---------------------------------------------------------------------------
// Tensor-core sliding-window attention. Pre-roped single-fp16 inputs.
// Block = (64 queries, h, b); keys [q0-128, q0+63] -> 192.
// S = Q*K (1-pass); PV = P*V (1-pass). ao written as fp16.
// ---------------------------------------------------------------------------
#define ARS 72
#define AQ  0
#define AK  (64*ARS*2)               // 9216
#define AV  (AK + 192*ARS*2)         // 36864
#define ARED (AV + 192*ARS*2)        // 64512
#define ATT_SMEM (ARED + 1024)       // 65536

__global__ __launch_bounds__(256, 2) void attn_hmma(
    const __half* __restrict__ qh, const __half* __restrict__ kh,
    const __half* __restrict__ vh,
    __half* __restrict__ ao)
{
    extern __shared__ __align__(16) char sm[];
    const uint32_t smb = smem_u32(sm);
    float* redm = (float*)(sm + ARED);
    float* reds = (float*)(sm + ARED + 512);
    float* scratch = (float*)sm;    // 16KB, reused post-S-phase

    const int q0 = blockIdx.x * 64;
    const int h  = blockIdx.y;
    const int bb = blockIdx.z;
    const int tid = threadIdx.x;
    const int wid = tid >> 5;
    const int lane = tid & 31;
    const size_t headbase = ((size_t)bb * H + h) * T * DH;
    const int k0 = q0 - 128;

    // ---- load: pure cp.async (512 Q + 2x1536 K/V 16B copies) ----
    for (int i = tid; i < 512; i += 256) {
        int r = i >> 3, s = i & 7;
        CP_ASYNC16(smb + AQ + (uint32_t)(r * ARS + s * 8) * 2,
                   qh + headbase + (size_t)(q0 + r) * DH + s * 8);
    }
    for (int i = tid; i < 1536; i += 256) {
        int r = i >> 3, s = i & 7;
        int kg = k0 + r;
        int kc = kg < 0 ? 0 : (kg >= T ? T - 1 : kg);
        size_t src = headbase + (size_t)kc * DH + s * 8;
        uint32_t off = (uint32_t)(r * ARS + s * 8) * 2;
        CP_ASYNC16(smb + AK + off, kh + src);
        CP_ASYNC16(smb + AV + off, vh + src);
    }
    CP_COMMIT();
    CP_WAIT0();
    __syncthreads();

    const int mt   = wid & 3;
    const int half = wid >> 2;
    const int row_r = lane >> 2;

    // ---- S = Q K^T (single pass) ----
    float p[12][4];
    #pragma unroll
    for (int nt = 0; nt < 12; nt++)
        #pragma unroll
        for (int e = 0; e < 4; e++) p[nt][e] = 0.f;

    const uint32_t qa_off = (uint32_t)((mt * 16 + (lane & 15)) * ARS
                                       + ((lane & 16) ? 8 : 0)) * 2;
    const uint32_t kb_row = (uint32_t)(half * 96 + (lane & 7) + ((lane & 16) ? 8 : 0));
    const uint32_t kb_coff = (uint32_t)((lane & 8) ? 8 : 0);

    #pragma unroll
    for (int kt = 0; kt < 4; kt++) {
        const uint32_t kc = (uint32_t)(kt * 16);
        uint32_t aq[4];
        LDM_X4(aq[0], aq[1], aq[2], aq[3], smb + AQ + qa_off + kc * 2);
        #pragma unroll
        for (int pp = 0; pp < 6; pp++) {
            uint32_t addr = smb + AK
                + ((kb_row + (uint32_t)(pp * 16)) * ARS + kc + kb_coff) * 2;
            uint32_t bh[4];
            LDM_X4(bh[0], bh[1], bh[2], bh[3], addr);
            #pragma unroll
            for (int sub = 0; sub < 2; sub++) {
                int nt = pp * 2 + sub;
                uint32_t bbh[2] = { bh[sub*2], bh[sub*2+1] };
                mma_f16(p[nt], aq, bbh);
            }
        }
    }

    // ---- mask (scale folded into Q at prep) ----
    {
        int qg1 = q0 + mt * 16 + row_r;
        int qg2 = qg1 + 8;
        #pragma unroll
        for (int nt = 0; nt < 12; nt++) {
            int cb = k0 + half * 96 + nt * 8 + 2 * (lane & 3);
            #pragma unroll
            for (int e = 0; e < 4; e++) {
                int kg = cb + (e & 1);
                int qg = (e & 2) ? qg2 : qg1;
                bool valid = (kg >= 0) && (kg <= qg) && (kg >= qg - 128);
                if (!valid) p[nt][e] = -1e30f;
            }
        }
    }

    // ---- softmax (cross-half via smem) ----
    float inv1, inv2;
    {
        float m0v = -1e30f, m1v = -1e30f;
        #pragma unroll
        for (int nt = 0; nt < 12; nt++) {
            m0v = fmaxf(m0v, fmaxf(p[nt][0], p[nt][1]));
            m1v = fmaxf(m1v, fmaxf(p[nt][2], p[nt][3]));
        }
        m0v = fmaxf(m0v, __shfl_xor_sync(0xffffffffu, m0v, 1));
        m0v = fmaxf(m0v, __shfl_xor_sync(0xffffffffu, m0v, 2));
        m1v = fmaxf(m1v, __shfl_xor_sync(0xffffffffu, m1v, 1));
        m1v = fmaxf(m1v, __shfl_xor_sync(0xffffffffu, m1v, 2));
        if ((lane & 3) == 0) {
            redm[half * 64 + mt * 16 + row_r]     = m0v;
            redm[half * 64 + mt * 16 + row_r + 8] = m1v;
        }
        __syncthreads();
        float M0 = fmaxf(redm[mt*16 + row_r],     redm[64 + mt*16 + row_r]);
        float M1 = fmaxf(redm[mt*16 + row_r + 8], redm[64 + mt*16 + row_r + 8]);

        float s0 = 0.f, s1 = 0.f;
        #pragma unroll
        for (int nt = 0; nt < 12; nt++) {
            p[nt][0] = __expf(p[nt][0] - M0); s0 += p[nt][0];
            p[nt][1] = __expf(p[nt][1] - M0); s0 += p[nt][1];
            p[nt][2] = __expf(p[nt][2] - M1); s1 += p[nt][2];
            p[nt][3] = __expf(p[nt][3] - M1); s1 += p[nt][3];
        }
        s0 += __shfl_xor_sync(0xffffffffu, s0, 1);
        s0 += __shfl_xor_sync(0xffffffffu, s0, 2);
        s1 += __shfl_xor_sync(0xffffffffu, s1, 1);
        s1 += __shfl_xor_sync(0xffffffffu, s1, 2);
        if ((lane & 3) == 0) {
            reds[half * 64 + mt * 16 + row_r]     = s0;
            reds[half * 64 + mt * 16 + row_r + 8] = s1;
        }
        __syncthreads();
        inv1 = 1.0f / (reds[mt*16 + row_r]     + reds[64 + mt*16 + row_r]);
        inv2 = 1.0f / (reds[mt*16 + row_r + 8] + reds[64 + mt*16 + row_r + 8]);
    }

    // ---- O = P V (single pass, ldmatrix.trans on V) ----
    float o[8][4];
    #pragma unroll
    for (int nt = 0; nt < 8; nt++)
        #pragma unroll
        for (int e = 0; e < 4; e++) o[nt][e] = 0.f;

    const uint32_t vb_row = (uint32_t)(half * 96 + (lane & 7) + ((lane & 8) ? 8 : 0));
    const uint32_t vb_coff = (uint32_t)((lane & 16) ? 8 : 0);

    #pragma unroll
    for (int kt = 0; kt < 6; kt++) {
        uint32_t pa[4];
        {
            float* e0 = p[2*kt]; float* e1 = p[2*kt+1];
            pa[0] = pkh(e0[0], e0[1]);
            pa[1] = pkh(e0[2], e0[3]);
            pa[2] = pkh(e1[0], e1[1]);
            pa[3] = pkh(e1[2], e1[3]);
        }
        #pragma unroll
        for (int dp = 0; dp < 4; dp++) {
            uint32_t addr = smb + AV
                + ((vb_row + (uint32_t)(kt * 16)) * ARS + (uint32_t)(dp * 16) + vb_coff) * 2;
            uint32_t vv[4];
            LDM_X4_T(vv[0], vv[1], vv[2], vv[3], addr);
            #pragma unroll
            for (int sub = 0; sub < 2; sub++) {
                int nt = dp * 2 + sub;
                uint32_t bb2[2] = { vv[sub*2], vv[sub*2+1] };
                mma_f16(o[nt], pa, bb2);
            }
        }
    }

    // ---- combine halves, write ao as fp16 ----
    if (half == 1) {
        #pragma unroll
        for (int nt = 0; nt < 8; nt++) {
            int col = nt * 8 + 2 * (lane & 3);
            *(float2*)&scratch[mt * 1024 + row_r * 64 + col] =
                make_float2(o[nt][0], o[nt][1]);
            *(float2*)&scratch[mt * 1024 + (row_r + 8) * 64 + col] =
                make_float2(o[nt][2], o[nt][3]);
        }
    }
    __syncthreads();
    if (half == 0) {
        int r1g = q0 + mt * 16 + row_r;
        int r2g = r1g + 8;
        #pragma unroll
        for (int nt = 0; nt < 8; nt++) {
            int col = nt * 8 + 2 * (lane & 3);
            float2 s1v = *(float2*)&scratch[mt * 1024 + row_r * 64 + col];
            float2 s2v = *(float2*)&scratch[mt * 1024 + (row_r + 8) * 64 + col];
            float w10 = (o[nt][0] + s1v.x) * inv1, w11 = (o[nt][1] + s1v.y) * inv1;
            float w20 = (o[nt][2] + s2v.x) * inv2, w21 = (o[nt][3] + s2v.y) * inv2;
            *(uint32_t*)(ao + ((size_t)bb * T + r1g) * DIM + h * 64 + col) = pkh(w10, w11);
            *(uint32_t*)(ao + ((size_t)bb * T + r2g) * DIM + h * 64 + col) = pkh(w20, w21);
        }
    }
}

// ---------------------------------------------------------------------------
extern "C" void kernel_launch(void* const* d_in, const int* in_sizes, int n_in,
                              void* d_out, int out_size)
{
    const float* x    = (const float*)d_in[0];
    const float* rope = (const float*)d_in[2];
    const float* Wq   = (const float*)d_in[3];
    const float* Wk   = (const float*)d_in[4];
    const float* Wv   = (const float*)d_in[5];
    const float* Wo   = (const float*)d_in[6];
    float* out = (float*)d_out;

    __half *xh, *whi, *wlo, *qh, *kh, *vh, *aoh;
    cudaGetSymbolAddress((void**)&xh,  g_xh);
    cudaGetSymbolAddress((void**)&whi, g_whi);
    cudaGetSymbolAddress((void**)&wlo, g_wlo);
    cudaGetSymbolAddress((void**)&qh,  g_qh);
    cudaGetSymbolAddress((void**)&kh,  g_kh);
    cudaGetSymbolAddress((void**)&vh,  g_vh);
    cudaGetSymbolAddress((void**)&aoh, g_aoh);

    cudaFuncSetAttribute(gemm_hmma, cudaFuncAttributeMaxDynamicSharedMemorySize, GEMM_SMEM);
    cudaFuncSetAttribute(attn_hmma, cudaFuncAttributeMaxDynamicSharedMemorySize, ATT_SMEM);

    const int xn4 = XSZ / 4;
    const int wn4tot = 4 * WSZ / 4;

    tohalf<<<xn4 / 256, 256>>>(x, xh, xn4);
    split_w4<<<wn4tot / 256, 256>>>(Wq, Wk, Wv, Wo, whi, wlo);

    // fused QKV (N = 3072, all single-pass)
    gemm_hmma<<<dim3(24, 32), 256, GEMM_SMEM>>>(xh, whi, nullptr,
                                                nullptr, qh, kh, vh, 1);

    // RoPE once per element, in-place (scale folded into Q)
    int nrope = B * H * T * 4;
    rope_prep<<<(nrope + 255) / 256, 256>>>(qh, kh, rope);

    attn_hmma<<<dim3(T / 64, H, B), 256, ATT_SMEM>>>(qh, kh, vh, aoh);

    // O projection (W index 3, 2-pass)
    gemm_hmma<<<dim3(8, 32), 256, GEMM_SMEM>>>(aoh, whi + 3*(size_t)WSZ, wlo,
                                               out, nullptr, nullptr, nullptr, 0);
}

// round 13
// speedup vs baseline: 2.3624x; 1.0167x over previous
#include <cuda_runtime.h>
#include <cuda_fp16.h>
#include <math.h>
#include <stdint.h>

#define B 2
#define T 2048
#define H 16
#define DH 64
#define DIM 1024
#define M_TOTAL (B*T)      // 4096
#define SZH (B*H*T*DH)     // 4194304
#define XSZ (M_TOTAL*DIM)  // 4194304
#define WSZ (DIM*DIM)      // 1048576
#define ATT_SCALE_L2 0.18033688011112042f   // 0.125 * log2(e)

// ---------------- scratch (device globals; allocation-free) ----------------
__device__ __half g_xh [XSZ];
__device__ __half g_whi[4*WSZ];
__device__ __half g_wlo[WSZ];      // only Wo needs a lo part
__device__ __half g_qh [SZH];
__device__ __half g_kh [SZH];
__device__ __half g_vh [SZH];
__device__ __half g_aoh[XSZ];

// ---------------- helpers ----------------
__device__ __forceinline__ uint32_t smem_u32(const void* p) {
    uint32_t a;
    asm("{ .reg .u64 t; cvta.to.shared.u64 t, %1; cvt.u32.u64 %0, t; }"
        : "=r"(a) : "l"(p));
    return a;
}

#define CP_ASYNC16(dst_u32, src_ptr) \
    asm volatile("cp.async.cg.shared.global [%0], [%1], 16;" :: "r"(dst_u32), "l"(src_ptr))
#define CP_COMMIT()  asm volatile("cp.async.commit_group;" ::: "memory")
#define CP_WAIT0()   asm volatile("cp.async.wait_group 0;" ::: "memory")
#define CP_WAIT1()   asm volatile("cp.async.wait_group 1;" ::: "memory")

#define LDM_X4(r0,r1,r2,r3, addr) \
    asm volatile("ldmatrix.sync.aligned.m8n8.x4.shared.b16 {%0,%1,%2,%3}, [%4];" \
                 : "=r"(r0), "=r"(r1), "=r"(r2), "=r"(r3) : "r"(addr))
#define LDM_X4_T(r0,r1,r2,r3, addr) \
    asm volatile("ldmatrix.sync.aligned.m8n8.x4.trans.shared.b16 {%0,%1,%2,%3}, [%4];" \
                 : "=r"(r0), "=r"(r1), "=r"(r2), "=r"(r3) : "r"(addr))

__device__ __forceinline__ void mma_f16(float* c, const uint32_t* a, const uint32_t* b) {
    asm volatile(
        "mma.sync.aligned.m16n8k16.row.col.f32.f16.f16.f32 "
        "{%0,%1,%2,%3}, {%4,%5,%6,%7}, {%8,%9}, {%0,%1,%2,%3};"
        : "+f"(c[0]), "+f"(c[1]), "+f"(c[2]), "+f"(c[3])
        : "r"(a[0]), "r"(a[1]), "r"(a[2]), "r"(a[3]), "r"(b[0]), "r"(b[1]));
}

__device__ __forceinline__ uint32_t pkh(float a, float b) {
    __half2 t = __floats2half2_rn(a, b);
    return *(uint32_t*)&t;
}

// ---------------------------------------------------------------------------
// fp32 -> fp16 (single)
// ---------------------------------------------------------------------------
__global__ void tohalf(const float* __restrict__ x, __half* __restrict__ o, int n4)
{
    int i = blockIdx.x * blockDim.x + threadIdx.x;
    if (i >= n4) return;
    float4 v = ((const float4*)x)[i];
    uint2 u;
    u.x = pkh(v.x, v.y);
    u.y = pkh(v.z, v.w);
    *(uint2*)(o + 4 * (size_t)i) = u;
}

// ---------------------------------------------------------------------------
// 4 weight matrices -> fp16 hi (+lo only for Wo)
// ---------------------------------------------------------------------------
__global__ void split_w4(const float* __restrict__ W0, const float* __restrict__ W1,
                         const float* __restrict__ W2, const float* __restrict__ W3,
                         __half* __restrict__ hi, __half* __restrict__ lo)
{
    int i = blockIdx.x * blockDim.x + threadIdx.x;  // over 4*WSZ/4
    int which = i >> 18;                            // WSZ/4 = 2^18
    int j = i & 0x3FFFF;
    const float* W = (which == 0) ? W0 : (which == 1) ? W1 : (which == 2) ? W2 : W3;
    float4 v = ((const float4*)W)[j];
    float f[4] = {v.x, v.y, v.z, v.w};
    __half h[4];
    #pragma unroll
    for (int e = 0; e < 4; e++) h[e] = __float2half_rn(f[e]);
    size_t base = (size_t)which * WSZ + (size_t)j * 4;
    uint2 uh;
    uh.x = pkh(__half2float(h[0]), __half2float(h[1]));
    uh.y = pkh(__half2float(h[2]), __half2float(h[3]));
    *(uint2*)(hi + base) = uh;
    if (which == 3) {
        uint2 ul;
        ul.x = pkh(f[0] - __half2float(h[0]), f[1] - __half2float(h[1]));
        ul.y = pkh(f[2] - __half2float(h[2]), f[3] - __half2float(h[3]));
        *(uint2*)(lo + (size_t)j * 4) = ul;
    }
}

// ---------------------------------------------------------------------------
// RoPE prep (IN-PLACE, vectorized): Q (folds scale*log2e) and K, single fp16.
// ---------------------------------------------------------------------------
__global__ void rope_prep(__half* __restrict__ q, __half* __restrict__ k,
                          const float* __restrict__ rope)
{
    int idx = blockIdx.x * blockDim.x + threadIdx.x;   // B*H*T*4
    if (idx >= B * H * T * 4) return;
    int d8   = (idx & 3) * 8;
    int rest = idx >> 2;
    int t    = rest & (T - 1);
    int bh   = rest >> 11;
    int bidx = bh >> 4;

    const float* pr = rope + ((size_t)bidx * T + t) * DH + d8;
    float p1[8], p2[8];
    *(float4*)(p1)     = *(const float4*)(pr);
    *(float4*)(p1 + 4) = *(const float4*)(pr + 4);
    *(float4*)(p2)     = *(const float4*)(pr + 32);
    *(float4*)(p2 + 4) = *(const float4*)(pr + 36);

    float c1[8], s1[8], c2[8], s2[8];
    #pragma unroll
    for (int e = 0; e < 8; e++) {
        __sincosf(p1[e], &s1[e], &c1[e]);
        __sincosf(p2[e], &s2[e], &c2[e]);
    }

    size_t base = (size_t)rest * DH + d8;

    {
        uint4 ua = *(uint4*)(q + base);
        uint4 ub = *(uint4*)(q + base + 32);
        __half* ha = (__half*)&ua;
        __half* hb = (__half*)&ub;
        uint4 oa, ob;
        __half* oa_h = (__half*)&oa;
        __half* ob_h = (__half*)&ob;
        #pragma unroll
        for (int e = 0; e < 8; e++) {
            float x1 = __half2float(ha[e]);
            float x2 = __half2float(hb[e]);
            oa_h[e] = __float2half_rn((x1 * c1[e] - x2 * s1[e]) * ATT_SCALE_L2);
            ob_h[e] = __float2half_rn((x2 * c2[e] + x1 * s2[e]) * ATT_SCALE_L2);
        }
        *(uint4*)(q + base)      = oa;
        *(uint4*)(q + base + 32) = ob;
    }
    {
        uint4 ua = *(uint4*)(k + base);
        uint4 ub = *(uint4*)(k + base + 32);
        __half* ha = (__half*)&ua;
        __half* hb = (__half*)&ub;
        uint4 oa, ob;
        __half* oa_h = (__half*)&oa;
        __half* ob_h = (__half*)&ob;
        #pragma unroll
        for (int e = 0; e < 8; e++) {
            float k1 = __half2float(ha[e]);
            float k2 = __half2float(hb[e]);
            oa_h[e] = __float2half_rn(k1 * c1[e] - k2 * s1[e]);
            ob_h[e] = __float2half_rn(k2 * c2[e] + k1 * s2[e]);
        }
        *(uint4*)(k + base)      = oa;
        *(uint4*)(k + base + 32) = ob;
    }
}

// ---------------------------------------------------------------------------
// Tensor-core GEMM, BK=64: C[m,n] = sum_k A[m,k]*W[n,k]
// mode 0: Cf fp32 row-major (O proj, 2-pass, 3 smem tiles)
// mode 1: QKV fused (grid.x=24, 1-pass, 2 smem tiles): which=n0>>10
// ---------------------------------------------------------------------------
#define BK64 64
#define GRS 72
#define GTILE (128*GRS*2)              // 18432 bytes
#define GEMM_SMEM_QKV (2*2*GTILE)      // 73728
#define GEMM_SMEM_O   (2*3*GTILE)      // 110592

__global__ __launch_bounds__(256) void gemm_hmma(
    const __half* __restrict__ A,
    const __half* __restrict__ Wh, const __half* __restrict__ Wl,
    float* __restrict__ Cf,
    __half* __restrict__ Cq, __half* __restrict__ Ck, __half* __restrict__ Cv,
    int mode)
{
    extern __shared__ __align__(16) char sm[];
    const uint32_t smb = smem_u32(sm);

    const int tid  = threadIdx.x;
    const int m0   = blockIdx.y * 128;
    const int n0   = blockIdx.x * 128;
    const int wid  = tid >> 5;
    const int lane = tid & 31;
    const int g    = lane >> 2;
    const int t2   = (lane & 3) * 2;
    const int wm   = (wid & 1) * 64;
    const int wn   = (wid >> 1) * 32;

    const int which = (mode == 1) ? (n0 >> 10) : 3;
    const bool use_lo = (mode == 0);
    const uint32_t buf_stride = (use_lo ? 3u : 2u) * GTILE;

    float acc[4][4][4];
    #pragma unroll
    for (int mt = 0; mt < 4; mt++)
        #pragma unroll
        for (int nt = 0; nt < 4; nt++)
            #pragma unroll
            for (int e = 0; e < 4; e++) acc[mt][nt][e] = 0.f;

    auto load_chunk = [&](int c, int buf) {
        const int k0 = c * BK64;
        const uint32_t bb = smb + (uint32_t)buf * buf_stride;
        const int niter = use_lo ? 12 : 8;
        for (int i = 0; i < niter; i++) {
            int idx = tid + i * 256;
            int arr = idx >> 10;          // tile index
            int rem = idx & 1023;
            int r   = rem >> 3;
            int c8  = (rem & 7) * 8;
            const __half* src;
            int rowbase;
            if (arr == 0)      { src = A;  rowbase = m0 + r; }
            else if (arr == 1) { src = Wh; rowbase = n0 + r; }
            else               { src = Wl; rowbase = n0 + r; }
            uint32_t dst = bb + (uint32_t)arr * GTILE + (uint32_t)(r * GRS + c8) * 2;
            CP_ASYNC16(dst, src + (size_t)rowbase * DIM + k0 + c8);
        }
    };

    const uint32_t a_off = (uint32_t)((wm + (lane & 15)) * GRS + ((lane & 16) ? 8 : 0));
    const uint32_t b_off = (uint32_t)((wn + (lane & 7) + ((lane & 16) ? 8 : 0)) * GRS
                                      + ((lane & 8) ? 8 : 0));

    const int NC = DIM / BK64;   // 16
    load_chunk(0, 0);
    CP_COMMIT();

    for (int c = 0; c < NC; c++) {
        if (c + 1 < NC) {
            load_chunk(c + 1, (c + 1) & 1);
            CP_COMMIT();
            CP_WAIT1();
        } else {
            CP_WAIT0();
        }
        __syncthreads();

        const uint32_t base = smb + (uint32_t)(c & 1) * buf_stride;

        #pragma unroll
        for (int ks = 0; ks < 4; ks++) {
            const uint32_t kc = (uint32_t)(ks * 16);
            uint32_t ar[4][4], wh[2][4], wl[2][4];
            #pragma unroll
            for (int mt = 0; mt < 4; mt++) {
                uint32_t addr = base + (a_off + (uint32_t)(mt * 16) * GRS + kc) * 2;
                LDM_X4(ar[mt][0], ar[mt][1], ar[mt][2], ar[mt][3], addr);
            }
            #pragma unroll
            for (int p = 0; p < 2; p++) {
                uint32_t addr = base + GTILE + (b_off + (uint32_t)(p * 16) * GRS + kc) * 2;
                LDM_X4(wh[p][0], wh[p][1], wh[p][2], wh[p][3], addr);
                if (use_lo) {
                    LDM_X4(wl[p][0], wl[p][1], wl[p][2], wl[p][3], addr + GTILE);
                }
            }
            #pragma unroll
            for (int mt = 0; mt < 4; mt++)
                #pragma unroll
                for (int nt = 0; nt < 4; nt++) {
                    uint32_t bh[2] = { wh[nt>>1][(nt&1)*2], wh[nt>>1][(nt&1)*2+1] };
                    mma_f16(acc[mt][nt], ar[mt], bh);
                    if (use_lo) {
                        uint32_t bl[2] = { wl[nt>>1][(nt&1)*2], wl[nt>>1][(nt&1)*2+1] };
                        mma_f16(acc[mt][nt], ar[mt], bl);
                    }
                }
        }
        __syncthreads();
    }

    // ---- epilogue ----
    if (mode == 0) {
        #pragma unroll
        for (int mt = 0; mt < 4; mt++) {
            int row0 = m0 + wm + mt * 16 + g;
            #pragma unroll
            for (int nt = 0; nt < 4; nt++) {
                int col = n0 + wn + nt * 8 + t2;
                *(float2*)(Cf + (size_t)row0 * DIM + col) =
                    make_float2(acc[mt][nt][0], acc[mt][nt][1]);
                *(float2*)(Cf + (size_t)(row0 + 8) * DIM + col) =
                    make_float2(acc[mt][nt][2], acc[mt][nt][3]);
            }
        }
    } else {
        __half* C = (which == 0) ? Cq : (which == 1) ? Ck : Cv;
        int n0w = n0 & 1023;
        #pragma unroll
        for (int mt = 0; mt < 4; mt++) {
            int row0 = m0 + wm + mt * 16 + g;
            int bb0 = row0 >> 11, t0 = row0 & (T - 1);
            int bb1 = (row0 + 8) >> 11, t1 = (row0 + 8) & (T - 1);
            #pragma unroll
            for (int nt = 0; nt < 4; nt++) {
                int col = n0w + wn + nt * 8 + t2;
                int h = col >> 6, d = col & 63;
                size_t i0 = (((size_t)bb0 * H + h) * T + t0) * DH + d;
                size_t i1 = (((size_t)bb1 * H + h) * T + t1) * DH + d;
                *(uint32_t*)(C + i0) = pkh(acc[mt][nt][0], acc[mt][nt][1]);
                *(uint32_t*)(C + i1) = pkh(acc[mt][nt][2], acc[mt][nt][3]);
            }
        }
    }
}

// ---------------------------------------------------------------------------
// Tensor-core sliding-window attention, flash-style half-merge.
// Block = (64 queries, h, b); keys [q0-128, q0+63] -> 192; 2 key-halves of 96.
// Loads: group A = Q+K, group B = V (overlaps S phase).
// Each half: local softmax (in-warp); merge via (m,s) rescale at combine.
// Q pre-scaled by 0.125*log2(e); exp2f throughout.
// ---------------------------------------------------------------------------
#define ARS 72
#define AQ  0
#define AK  (64*ARS*2)               // 9216
#define AV  (AK + 192*ARS*2)         // 36864
#define ARED (AV + 192*ARS*2)        // 64512
#define ATT_SMEM (ARED + 1024)       // 65536

__global__ __launch_bounds__(256, 2) void attn_hmma(
    const __half* __restrict__ qh, const __half* __restrict__ kh,
    const __half* __restrict__ vh,
    __half* __restrict__ ao)
{
    extern __shared__ __align__(16) char sm[];
    const uint32_t smb = smem_u32(sm);
    float* redm = (float*)(sm + ARED);          // [64] half-1 local max
    float* reds = (float*)(sm + ARED + 256);    // [64] half-1 local sum
    float* scratch = (float*)sm;                // 16KB, overlaps AQ+AK (dead post-S)

    const int q0 = blockIdx.x * 64;
    const int h  = blockIdx.y;
    const int bb = blockIdx.z;
    const int tid = threadIdx.x;
    const int wid = tid >> 5;
    const int lane = tid & 31;
    const size_t headbase = ((size_t)bb * H + h) * T * DH;
    const int k0 = q0 - 128;

    // ---- group A: Q + K ----
    for (int i = tid; i < 512; i += 256) {
        int r = i >> 3, s = i & 7;
        CP_ASYNC16(smb + AQ + (uint32_t)(r * ARS + s * 8) * 2,
                   qh + headbase + (size_t)(q0 + r) * DH + s * 8);
    }
    for (int i = tid; i < 1536; i += 256) {
        int r = i >> 3, s = i & 7;
        int kg = k0 + r;
        int kc = kg < 0 ? 0 : (kg >= T ? T - 1 : kg);
        CP_ASYNC16(smb + AK + (uint32_t)(r * ARS + s * 8) * 2,
                   kh + headbase + (size_t)kc * DH + s * 8);
    }
    CP_COMMIT();
    // ---- group B: V (overlaps S) ----
    for (int i = tid; i < 1536; i += 256) {
        int r = i >> 3, s = i & 7;
        int kg = k0 + r;
        int kc = kg < 0 ? 0 : (kg >= T ? T - 1 : kg);
        CP_ASYNC16(smb + AV + (uint32_t)(r * ARS + s * 8) * 2,
                   vh + headbase + (size_t)kc * DH + s * 8);
    }
    CP_COMMIT();
    CP_WAIT1();          // group A complete (V may still be in flight)
    __syncthreads();

    const int mt   = wid & 3;
    const int half = wid >> 2;
    const int row_r = lane >> 2;

    // ---- S = Q K^T (single pass, log2-scaled) ----
    float p[12][4];
    #pragma unroll
    for (int nt = 0; nt < 12; nt++)
        #pragma unroll
        for (int e = 0; e < 4; e++) p[nt][e] = 0.f;

    const uint32_t qa_off = (uint32_t)((mt * 16 + (lane & 15)) * ARS
                                       + ((lane & 16) ? 8 : 0)) * 2;
    const uint32_t kb_row = (uint32_t)(half * 96 + (lane & 7) + ((lane & 16) ? 8 : 0));
    const uint32_t kb_coff = (uint32_t)((lane & 8) ? 8 : 0);

    #pragma unroll
    for (int kt = 0; kt < 4; kt++) {
        const uint32_t kc = (uint32_t)(kt * 16);
        uint32_t aq[4];
        LDM_X4(aq[0], aq[1], aq[2], aq[3], smb + AQ + qa_off + kc * 2);
        #pragma unroll
        for (int pp = 0; pp < 6; pp++) {
            uint32_t addr = smb + AK
                + ((kb_row + (uint32_t)(pp * 16)) * ARS + kc + kb_coff) * 2;
            uint32_t bh[4];
            LDM_X4(bh[0], bh[1], bh[2], bh[3], addr);
            #pragma unroll
            for (int sub = 0; sub < 2; sub++) {
                int nt = pp * 2 + sub;
                uint32_t bbh[2] = { bh[sub*2], bh[sub*2+1] };
                mma_f16(p[nt], aq, bbh);
            }
        }
    }

    // ---- mask ----
    {
        int qg1 = q0 + mt * 16 + row_r;
        int qg2 = qg1 + 8;
        #pragma unroll
        for (int nt = 0; nt < 12; nt++) {
            int cb = k0 + half * 96 + nt * 8 + 2 * (lane & 3);
            #pragma unroll
            for (int e = 0; e < 4; e++) {
                int kg = cb + (e & 1);
                int qg = (e & 2) ? qg2 : qg1;
                bool valid = (kg >= 0) && (kg <= qg) && (kg >= qg - 128);
                if (!valid) p[nt][e] = -1e30f;
            }
        }
    }

    // ---- local softmax (in-warp only; no cross-half sync) ----
    float mloc1, mloc2, sloc1, sloc2;
    {
        float m0v = -1e30f, m1v = -1e30f;
        #pragma unroll
        for (int nt = 0; nt < 12; nt++) {
            m0v = fmaxf(m0v, fmaxf(p[nt][0], p[nt][1]));
            m1v = fmaxf(m1v, fmaxf(p[nt][2], p[nt][3]));
        }
        m0v = fmaxf(m0v, __shfl_xor_sync(0xffffffffu, m0v, 1));
        m0v = fmaxf(m0v, __shfl_xor_sync(0xffffffffu, m0v, 2));
        m1v = fmaxf(m1v, __shfl_xor_sync(0xffffffffu, m1v, 1));
        m1v = fmaxf(m1v, __shfl_xor_sync(0xffffffffu, m1v, 2));

        float s0 = 0.f, s1 = 0.f;
        #pragma unroll
        for (int nt = 0; nt < 12; nt++) {
            p[nt][0] = exp2f(p[nt][0] - m0v); s0 += p[nt][0];
            p[nt][1] = exp2f(p[nt][1] - m0v); s0 += p[nt][1];
            p[nt][2] = exp2f(p[nt][2] - m1v); s1 += p[nt][2];
            p[nt][3] = exp2f(p[nt][3] - m1v); s1 += p[nt][3];
        }
        s0 += __shfl_xor_sync(0xffffffffu, s0, 1);
        s0 += __shfl_xor_sync(0xffffffffu, s0, 2);
        s1 += __shfl_xor_sync(0xffffffffu, s1, 1);
        s1 += __shfl_xor_sync(0xffffffffu, s1, 2);
        mloc1 = m0v; mloc2 = m1v; sloc1 = s0; sloc2 = s1;
    }

    // ---- wait V, then O = P V (unnormalized) ----
    CP_WAIT0();
    __syncthreads();

    float o[8][4];
    #pragma unroll
    for (int nt = 0; nt < 8; nt++)
        #pragma unroll
        for (int e = 0; e < 4; e++) o[nt][e] = 0.f;

    const uint32_t vb_row = (uint32_t)(half * 96 + (lane & 7) + ((lane & 8) ? 8 : 0));
    const uint32_t vb_coff = (uint32_t)((lane & 16) ? 8 : 0);

    #pragma unroll
    for (int kt = 0; kt < 6; kt++) {
        uint32_t pa[4];
        {
            float* e0 = p[2*kt]; float* e1 = p[2*kt+1];
            pa[0] = pkh(e0[0], e0[1]);
            pa[1] = pkh(e0[2], e0[3]);
            pa[2] = pkh(e1[0], e1[1]);
            pa[3] = pkh(e1[2], e1[3]);
        }
        #pragma unroll
        for (int dp = 0; dp < 4; dp++) {
            uint32_t addr = smb + AV
                + ((vb_row + (uint32_t)(kt * 16)) * ARS + (uint32_t)(dp * 16) + vb_coff) * 2;
            uint32_t vv[4];
            LDM_X4_T(vv[0], vv[1], vv[2], vv[3], addr);
            #pragma unroll
            for (int sub = 0; sub < 2; sub++) {
                int nt = dp * 2 + sub;
                uint32_t bb2[2] = { vv[sub*2], vv[sub*2+1] };
                mma_f16(o[nt], pa, bb2);
            }
        }
    }

    // ---- combine halves (flash merge) and write ao ----
    if (half == 1) {
        #pragma unroll
        for (int nt = 0; nt < 8; nt++) {
            int col = nt * 8 + 2 * (lane & 3);
            *(float2*)&scratch[mt * 1024 + row_r * 64 + col] =
                make_float2(o[nt][0], o[nt][1]);
            *(float2*)&scratch[mt * 1024 + (row_r + 8) * 64 + col] =
                make_float2(o[nt][2], o[nt][3]);
        }
        if ((lane & 3) == 0) {
            redm[mt * 16 + row_r]     = mloc1;
            redm[mt * 16 + row_r + 8] = mloc2;
            reds[mt * 16 + row_r]     = sloc1;
            reds[mt * 16 + row_r + 8] = sloc2;
        }
    }
    __syncthreads();
    if (half == 0) {
        int r1g = q0 + mt * 16 + row_r;
        int r2g = r1g + 8;
        float m1o = redm[mt * 16 + row_r],     s1o = reds[mt * 16 + row_r];
        float m2o = redm[mt * 16 + row_r + 8], s2o = reds[mt * 16 + row_r + 8];
        float M1 = fmaxf(mloc1, m1o), M2 = fmaxf(mloc2, m2o);
        float wa1 = exp2f(mloc1 - M1), wb1 = exp2f(m1o - M1);
        float wa2 = exp2f(mloc2 - M2), wb2 = exp2f(m2o - M2);
        float inv1 = 1.0f / (sloc1 * wa1 + s1o * wb1);
        float inv2 = 1.0f / (sloc2 * wa2 + s2o * wb2);
        #pragma unroll
        for (int nt = 0; nt < 8; nt++) {
            int col = nt * 8 + 2 * (lane & 3);
            float2 s1v = *(float2*)&scratch[mt * 1024 + row_r * 64 + col];
            float2 s2v = *(float2*)&scratch[mt * 1024 + (row_r + 8) * 64 + col];
            float w10 = (o[nt][0] * wa1 + s1v.x * wb1) * inv1;
            float w11 = (o[nt][1] * wa1 + s1v.y * wb1) * inv1;
            float w20 = (o[nt][2] * wa2 + s2v.x * wb2) * inv2;
            float w21 = (o[nt][3] * wa2 + s2v.y * wb2) * inv2;
            *(uint32_t*)(ao + ((size_t)bb * T + r1g) * DIM + h * 64 + col) = pkh(w10, w11);
            *(uint32_t*)(ao + ((size_t)bb * T + r2g) * DIM + h * 64 + col) = pkh(w20, w21);
        }
    }
}

// ---------------------------------------------------------------------------
extern "C" void kernel_launch(void* const* d_in, const int* in_sizes, int n_in,
                              void* d_out, int out_size)
{
    const float* x    = (const float*)d_in[0];
    const float* rope = (const float*)d_in[2];
    const float* Wq   = (const float*)d_in[3];
    const float* Wk   = (const float*)d_in[4];
    const float* Wv   = (const float*)d_in[5];
    const float* Wo   = (const float*)d_in[6];
    float* out = (float*)d_out;

    __half *xh, *whi, *wlo, *qh, *kh, *vh, *aoh;
    cudaGetSymbolAddress((void**)&xh,  g_xh);
    cudaGetSymbolAddress((void**)&whi, g_whi);
    cudaGetSymbolAddress((void**)&wlo, g_wlo);
    cudaGetSymbolAddress((void**)&qh,  g_qh);
    cudaGetSymbolAddress((void**)&kh,  g_kh);
    cudaGetSymbolAddress((void**)&vh,  g_vh);
    cudaGetSymbolAddress((void**)&aoh, g_aoh);

    cudaFuncSetAttribute(gemm_hmma, cudaFuncAttributeMaxDynamicSharedMemorySize, GEMM_SMEM_O);
    cudaFuncSetAttribute(attn_hmma, cudaFuncAttributeMaxDynamicSharedMemorySize, ATT_SMEM);

    const int xn4 = XSZ / 4;
    const int wn4tot = 4 * WSZ / 4;

    tohalf<<<xn4 / 256, 256>>>(x, xh, xn4);
    split_w4<<<wn4tot / 256, 256>>>(Wq, Wk, Wv, Wo, whi, wlo);

    // fused QKV (N = 3072, 1-pass, 2-tile smem)
    gemm_hmma<<<dim3(24, 32), 256, GEMM_SMEM_QKV>>>(xh, whi, nullptr,
                                                    nullptr, qh, kh, vh, 1);

    int nrope = B * H * T * 4;
    rope_prep<<<(nrope + 255) / 256, 256>>>(qh, kh, rope);

    attn_hmma<<<dim3(T / 64, H, B), 256, ATT_SMEM>>>(qh, kh, vh, aoh);

    // O projection (2-pass, 3-tile smem)
    gemm_hmma<<<dim3(8, 32), 256, GEMM_SMEM_O>>>(aoh, whi + 3*(size_t)WSZ, wlo,
                                                 out, nullptr, nullptr, nullptr, 0);
}

// round 14
// speedup vs baseline: 3.6152x; 1.5303x over previous
#include <cuda_runtime.h>
#include <cuda_fp16.h>
#include <math.h>
#include <stdint.h>

#define B 2
#define T 2048
#define H 16
#define DH 64
#define DIM 1024
#define M_TOTAL (B*T)      // 4096
#define SZH (B*H*T*DH)     // 4194304
#define XSZ (M_TOTAL*DIM)  // 4194304
#define WSZ (DIM*DIM)      // 1048576
#define ATT_SCALE_L2 0.18033688011112042f   // 0.125 * log2(e)

// ---------------- scratch (device globals; allocation-free) ----------------
__device__ __half g_xh [XSZ];
__device__ __half g_whi[4*WSZ];
__device__ __half g_qh [SZH];
__device__ __half g_kh [SZH];
__device__ __half g_vh [SZH];
__device__ __half g_aoh[XSZ];

// ---------------- helpers ----------------
__device__ __forceinline__ uint32_t smem_u32(const void* p) {
    uint32_t a;
    asm("{ .reg .u64 t; cvta.to.shared.u64 t, %1; cvt.u32.u64 %0, t; }"
        : "=r"(a) : "l"(p));
    return a;
}

#define CP_ASYNC16(dst_u32, src_ptr) \
    asm volatile("cp.async.cg.shared.global [%0], [%1], 16;" :: "r"(dst_u32), "l"(src_ptr))
#define CP_COMMIT()  asm volatile("cp.async.commit_group;" ::: "memory")
#define CP_WAIT0()   asm volatile("cp.async.wait_group 0;" ::: "memory")
#define CP_WAIT1()   asm volatile("cp.async.wait_group 1;" ::: "memory")

#define LDM_X4(r0,r1,r2,r3, addr) \
    asm volatile("ldmatrix.sync.aligned.m8n8.x4.shared.b16 {%0,%1,%2,%3}, [%4];" \
                 : "=r"(r0), "=r"(r1), "=r"(r2), "=r"(r3) : "r"(addr))
#define LDM_X4_T(r0,r1,r2,r3, addr) \
    asm volatile("ldmatrix.sync.aligned.m8n8.x4.trans.shared.b16 {%0,%1,%2,%3}, [%4];" \
                 : "=r"(r0), "=r"(r1), "=r"(r2), "=r"(r3) : "r"(addr))

__device__ __forceinline__ void mma_f16(float* c, const uint32_t* a, const uint32_t* b) {
    asm volatile(
        "mma.sync.aligned.m16n8k16.row.col.f32.f16.f16.f32 "
        "{%0,%1,%2,%3}, {%4,%5,%6,%7}, {%8,%9}, {%0,%1,%2,%3};"
        : "+f"(c[0]), "+f"(c[1]), "+f"(c[2]), "+f"(c[3])
        : "r"(a[0]), "r"(a[1]), "r"(a[2]), "r"(a[3]), "r"(b[0]), "r"(b[1]));
}

__device__ __forceinline__ uint32_t pkh(float a, float b) {
    __half2 t = __floats2half2_rn(a, b);
    return *(uint32_t*)&t;
}

// ---------------------------------------------------------------------------
// fp32 -> fp16 (single)
// ---------------------------------------------------------------------------
__global__ void tohalf(const float* __restrict__ x, __half* __restrict__ o, int n4)
{
    int i = blockIdx.x * blockDim.x + threadIdx.x;
    if (i >= n4) return;
    float4 v = ((const float4*)x)[i];
    uint2 u;
    u.x = pkh(v.x, v.y);
    u.y = pkh(v.z, v.w);
    *(uint2*)(o + 4 * (size_t)i) = u;
}

// ---------------------------------------------------------------------------
// 4 weight matrices -> fp16 (single, one launch)
// ---------------------------------------------------------------------------
__global__ void split_w4(const float* __restrict__ W0, const float* __restrict__ W1,
                         const float* __restrict__ W2, const float* __restrict__ W3,
                         __half* __restrict__ hi)
{
    int i = blockIdx.x * blockDim.x + threadIdx.x;  // over 4*WSZ/4
    int which = i >> 18;                            // WSZ/4 = 2^18
    int j = i & 0x3FFFF;
    const float* W = (which == 0) ? W0 : (which == 1) ? W1 : (which == 2) ? W2 : W3;
    float4 v = ((const float4*)W)[j];
    uint2 uh;
    uh.x = pkh(v.x, v.y);
    uh.y = pkh(v.z, v.w);
    *(uint2*)(hi + (size_t)which * WSZ + (size_t)j * 4) = uh;
}

// ---------------------------------------------------------------------------
// RoPE prep (IN-PLACE, vectorized): Q (folds scale*log2e) and K, single fp16.
// ---------------------------------------------------------------------------
__global__ void rope_prep(__half* __restrict__ q, __half* __restrict__ k,
                          const float* __restrict__ rope)
{
    int idx = blockIdx.x * blockDim.x + threadIdx.x;   // B*H*T*4
    if (idx >= B * H * T * 4) return;
    int d8   = (idx & 3) * 8;
    int rest = idx >> 2;
    int t    = rest & (T - 1);
    int bh   = rest >> 11;
    int bidx = bh >> 4;

    const float* pr = rope + ((size_t)bidx * T + t) * DH + d8;
    float p1[8], p2[8];
    *(float4*)(p1)     = *(const float4*)(pr);
    *(float4*)(p1 + 4) = *(const float4*)(pr + 4);
    *(float4*)(p2)     = *(const float4*)(pr + 32);
    *(float4*)(p2 + 4) = *(const float4*)(pr + 36);

    float c1[8], s1[8], c2[8], s2[8];
    #pragma unroll
    for (int e = 0; e < 8; e++) {
        __sincosf(p1[e], &s1[e], &c1[e]);
        __sincosf(p2[e], &s2[e], &c2[e]);
    }

    size_t base = (size_t)rest * DH + d8;

    {
        uint4 ua = *(uint4*)(q + base);
        uint4 ub = *(uint4*)(q + base + 32);
        __half* ha = (__half*)&ua;
        __half* hb = (__half*)&ub;
        uint4 oa, ob;
        __half* oa_h = (__half*)&oa;
        __half* ob_h = (__half*)&ob;
        #pragma unroll
        for (int e = 0; e < 8; e++) {
            float x1 = __half2float(ha[e]);
            float x2 = __half2float(hb[e]);
            oa_h[e] = __float2half_rn((x1 * c1[e] - x2 * s1[e]) * ATT_SCALE_L2);
            ob_h[e] = __float2half_rn((x2 * c2[e] + x1 * s2[e]) * ATT_SCALE_L2);
        }
        *(uint4*)(q + base)      = oa;
        *(uint4*)(q + base + 32) = ob;
    }
    {
        uint4 ua = *(uint4*)(k + base);
        uint4 ub = *(uint4*)(k + base + 32);
        __half* ha = (__half*)&ua;
        __half* hb = (__half*)&ub;
        uint4 oa, ob;
        __half* oa_h = (__half*)&oa;
        __half* ob_h = (__half*)&ob;
        #pragma unroll
        for (int e = 0; e < 8; e++) {
            float k1 = __half2float(ha[e]);
            float k2 = __half2float(hb[e]);
            oa_h[e] = __float2half_rn(k1 * c1[e] - k2 * s1[e]);
            ob_h[e] = __float2half_rn(k2 * c2[e] + k1 * s2[e]);
        }
        *(uint4*)(k + base)      = oa;
        *(uint4*)(k + base + 32) = ob;
    }
}

// ---------------------------------------------------------------------------
// Tensor-core GEMM, BK=64, single-pass fp16: C[m,n] = sum_k A[m,k]*W[n,k]
// mode 0: Cf fp32 row-major (O proj)
// mode 1: QKV fused (grid.x=24): which=n0>>10 -> Cq/Ck/Cv fp16 scatter
// ---------------------------------------------------------------------------
#define BK64 64
#define GRS 72
#define GTILE (128*GRS*2)              // 18432 bytes
#define GEMM_SMEM (2*2*GTILE)          // 73728

__global__ __launch_bounds__(256) void gemm_hmma(
    const __half* __restrict__ A,
    const __half* __restrict__ Wh,
    float* __restrict__ Cf,
    __half* __restrict__ Cq, __half* __restrict__ Ck, __half* __restrict__ Cv,
    int mode)
{
    extern __shared__ __align__(16) char sm[];
    const uint32_t smb = smem_u32(sm);

    const int tid  = threadIdx.x;
    const int m0   = blockIdx.y * 128;
    const int n0   = blockIdx.x * 128;
    const int wid  = tid >> 5;
    const int lane = tid & 31;
    const int g    = lane >> 2;
    const int t2   = (lane & 3) * 2;
    const int wm   = (wid & 1) * 64;
    const int wn   = (wid >> 1) * 32;

    float acc[4][4][4];
    #pragma unroll
    for (int mt = 0; mt < 4; mt++)
        #pragma unroll
        for (int nt = 0; nt < 4; nt++)
            #pragma unroll
            for (int e = 0; e < 4; e++) acc[mt][nt][e] = 0.f;

    auto load_chunk = [&](int c, int buf) {
        const int k0 = c * BK64;
        const uint32_t bb = smb + (uint32_t)buf * (2u * GTILE);
        #pragma unroll
        for (int i = 0; i < 8; i++) {
            int idx = tid + i * 256;      // 0..2047
            int arr = idx >> 10;          // 0..1
            int rem = idx & 1023;
            int r   = rem >> 3;
            int c8  = (rem & 7) * 8;
            const __half* src = arr ? Wh : A;
            int rowbase = (arr ? n0 : m0) + r;
            uint32_t dst = bb + (uint32_t)arr * GTILE + (uint32_t)(r * GRS + c8) * 2;
            CP_ASYNC16(dst, src + (size_t)rowbase * DIM + k0 + c8);
        }
    };

    const uint32_t a_off = (uint32_t)((wm + (lane & 15)) * GRS + ((lane & 16) ? 8 : 0));
    const uint32_t b_off = (uint32_t)((wn + (lane & 7) + ((lane & 16) ? 8 : 0)) * GRS
                                      + ((lane & 8) ? 8 : 0));

    const int NC = DIM / BK64;   // 16
    load_chunk(0, 0);
    CP_COMMIT();

    for (int c = 0; c < NC; c++) {
        if (c + 1 < NC) {
            load_chunk(c + 1, (c + 1) & 1);
            CP_COMMIT();
            CP_WAIT1();
        } else {
            CP_WAIT0();
        }
        __syncthreads();

        const uint32_t base = smb + (uint32_t)(c & 1) * (2u * GTILE);

        #pragma unroll
        for (int ks = 0; ks < 4; ks++) {
            const uint32_t kc = (uint32_t)(ks * 16);
            uint32_t ar[4][4], wh[2][4];
            #pragma unroll
            for (int mt = 0; mt < 4; mt++) {
                uint32_t addr = base + (a_off + (uint32_t)(mt * 16) * GRS + kc) * 2;
                LDM_X4(ar[mt][0], ar[mt][1], ar[mt][2], ar[mt][3], addr);
            }
            #pragma unroll
            for (int p = 0; p < 2; p++) {
                uint32_t addr = base + GTILE + (b_off + (uint32_t)(p * 16) * GRS + kc) * 2;
                LDM_X4(wh[p][0], wh[p][1], wh[p][2], wh[p][3], addr);
            }
            #pragma unroll
            for (int mt = 0; mt < 4; mt++)
                #pragma unroll
                for (int nt = 0; nt < 4; nt++) {
                    uint32_t bh[2] = { wh[nt>>1][(nt&1)*2], wh[nt>>1][(nt&1)*2+1] };
                    mma_f16(acc[mt][nt], ar[mt], bh);
                }
        }
        __syncthreads();
    }

    // ---- epilogue ----
    if (mode == 0) {
        #pragma unroll
        for (int mt = 0; mt < 4; mt++) {
            int row0 = m0 + wm + mt * 16 + g;
            #pragma unroll
            for (int nt = 0; nt < 4; nt++) {
                int col = n0 + wn + nt * 8 + t2;
                *(float2*)(Cf + (size_t)row0 * DIM + col) =
                    make_float2(acc[mt][nt][0], acc[mt][nt][1]);
                *(float2*)(Cf + (size_t)(row0 + 8) * DIM + col) =
                    make_float2(acc[mt][nt][2], acc[mt][nt][3]);
            }
        }
    } else {
        int which = n0 >> 10;
        __half* C = (which == 0) ? Cq : (which == 1) ? Ck : Cv;
        int n0w = n0 & 1023;
        #pragma unroll
        for (int mt = 0; mt < 4; mt++) {
            int row0 = m0 + wm + mt * 16 + g;
            int bb0 = row0 >> 11, t0 = row0 & (T - 1);
            int bb1 = (row0 + 8) >> 11, t1 = (row0 + 8) & (T - 1);
            #pragma unroll
            for (int nt = 0; nt < 4; nt++) {
                int col = n0w + wn + nt * 8 + t2;
                int h = col >> 6, d = col & 63;
                size_t i0 = (((size_t)bb0 * H + h) * T + t0) * DH + d;
                size_t i1 = (((size_t)bb1 * H + h) * T + t1) * DH + d;
                *(uint32_t*)(C + i0) = pkh(acc[mt][nt][0], acc[mt][nt][1]);
                *(uint32_t*)(C + i1) = pkh(acc[mt][nt][2], acc[mt][nt][3]);
            }
        }
    }
}

// ---------------------------------------------------------------------------
// Tensor-core sliding-window attention, flash-style half-merge + band skip.
// Block = (64 queries, h, b); keys [q0-128, q0+63] -> 192; 2 key-halves of 96.
// Warp (mt, half) needs only key-chunks: half0 pp in [mt,5], half1 pp in [0,2+mt]
// (25% of S and PV MMAs skipped; skipped tiles are fully masked -> weight 0).
// ---------------------------------------------------------------------------
#define ARS 72
#define AQ  0
#define AK  (64*ARS*2)               // 9216
#define AV  (AK + 192*ARS*2)         // 36864
#define ARED (AV + 192*ARS*2)        // 64512
#define ATT_SMEM (ARED + 1024)       // 65536

__global__ __launch_bounds__(256, 2) void attn_hmma(
    const __half* __restrict__ qh, const __half* __restrict__ kh,
    const __half* __restrict__ vh,
    __half* __restrict__ ao)
{
    extern __shared__ __align__(16) char sm[];
    const uint32_t smb = smem_u32(sm);
    float* redm = (float*)(sm + ARED);
    float* reds = (float*)(sm + ARED + 256);
    float* scratch = (float*)sm;                // 16KB, overlaps AQ+AK (dead post-S)

    const int q0 = blockIdx.x * 64;
    const int h  = blockIdx.y;
    const int bb = blockIdx.z;
    const int tid = threadIdx.x;
    const int wid = tid >> 5;
    const int lane = tid & 31;
    const size_t headbase = ((size_t)bb * H + h) * T * DH;
    const int k0 = q0 - 128;

    // ---- group A: Q + K ----
    for (int i = tid; i < 512; i += 256) {
        int r = i >> 3, s = i & 7;
        CP_ASYNC16(smb + AQ + (uint32_t)(r * ARS + s * 8) * 2,
                   qh + headbase + (size_t)(q0 + r) * DH + s * 8);
    }
    for (int i = tid; i < 1536; i += 256) {
        int r = i >> 3, s = i & 7;
        int kg = k0 + r;
        int kc = kg < 0 ? 0 : (kg >= T ? T - 1 : kg);
        CP_ASYNC16(smb + AK + (uint32_t)(r * ARS + s * 8) * 2,
                   kh + headbase + (size_t)kc * DH + s * 8);
    }
    CP_COMMIT();
    // ---- group B: V (overlaps S) ----
    for (int i = tid; i < 1536; i += 256) {
        int r = i >> 3, s = i & 7;
        int kg = k0 + r;
        int kc = kg < 0 ? 0 : (kg >= T ? T - 1 : kg);
        CP_ASYNC16(smb + AV + (uint32_t)(r * ARS + s * 8) * 2,
                   vh + headbase + (size_t)kc * DH + s * 8);
    }
    CP_COMMIT();
    CP_WAIT1();
    __syncthreads();

    const int mt   = wid & 3;
    const int half = wid >> 2;
    const int row_r = lane >> 2;

    const int pp_lo = half ? 0 : mt;
    const int pp_hi = half ? (2 + mt) : 5;

    // ---- S = Q K^T (band-skipped) ----
    float p[12][4];
    #pragma unroll
    for (int nt = 0; nt < 12; nt++)
        #pragma unroll
        for (int e = 0; e < 4; e++) p[nt][e] = 0.f;

    const uint32_t qa_off = (uint32_t)((mt * 16 + (lane & 15)) * ARS
                                       + ((lane & 16) ? 8 : 0)) * 2;
    const uint32_t kb_row = (uint32_t)(half * 96 + (lane & 7) + ((lane & 16) ? 8 : 0));
    const uint32_t kb_coff = (uint32_t)((lane & 8) ? 8 : 0);

    #pragma unroll
    for (int kt = 0; kt < 4; kt++) {
        const uint32_t kc = (uint32_t)(kt * 16);
        uint32_t aq[4];
        LDM_X4(aq[0], aq[1], aq[2], aq[3], smb + AQ + qa_off + kc * 2);
        #pragma unroll
        for (int pp = 0; pp < 6; pp++) {
            if (pp < pp_lo || pp > pp_hi) continue;
            uint32_t addr = smb + AK
                + ((kb_row + (uint32_t)(pp * 16)) * ARS + kc + kb_coff) * 2;
            uint32_t bh[4];
            LDM_X4(bh[0], bh[1], bh[2], bh[3], addr);
            #pragma unroll
            for (int sub = 0; sub < 2; sub++) {
                int nt = pp * 2 + sub;
                uint32_t bbh[2] = { bh[sub*2], bh[sub*2+1] };
                mma_f16(p[nt], aq, bbh);
            }
        }
    }

    // ---- mask ----
    {
        int qg1 = q0 + mt * 16 + row_r;
        int qg2 = qg1 + 8;
        #pragma unroll
        for (int nt = 0; nt < 12; nt++) {
            int cb = k0 + half * 96 + nt * 8 + 2 * (lane & 3);
            #pragma unroll
            for (int e = 0; e < 4; e++) {
                int kg = cb + (e & 1);
                int qg = (e & 2) ? qg2 : qg1;
                bool valid = (kg >= 0) && (kg <= qg) && (kg >= qg - 128);
                if (!valid) p[nt][e] = -1e30f;
            }
        }
    }

    // ---- local softmax (in-warp only) ----
    float mloc1, mloc2, sloc1, sloc2;
    {
        float m0v = -1e30f, m1v = -1e30f;
        #pragma unroll
        for (int nt = 0; nt < 12; nt++) {
            m0v = fmaxf(m0v, fmaxf(p[nt][0], p[nt][1]));
            m1v = fmaxf(m1v, fmaxf(p[nt][2], p[nt][3]));
        }
        m0v = fmaxf(m0v, __shfl_xor_sync(0xffffffffu, m0v, 1));
        m0v = fmaxf(m0v, __shfl_xor_sync(0xffffffffu, m0v, 2));
        m1v = fmaxf(m1v, __shfl_xor_sync(0xffffffffu, m1v, 1));
        m1v = fmaxf(m1v, __shfl_xor_sync(0xffffffffu, m1v, 2));

        float s0 = 0.f, s1 = 0.f;
        #pragma unroll
        for (int nt = 0; nt < 12; nt++) {
            p[nt][0] = exp2f(p[nt][0] - m0v); s0 += p[nt][0];
            p[nt][1] = exp2f(p[nt][1] - m0v); s0 += p[nt][1];
            p[nt][2] = exp2f(p[nt][2] - m1v); s1 += p[nt][2];
            p[nt][3] = exp2f(p[nt][3] - m1v); s1 += p[nt][3];
        }
        s0 += __shfl_xor_sync(0xffffffffu, s0, 1);
        s0 += __shfl_xor_sync(0xffffffffu, s0, 2);
        s1 += __shfl_xor_sync(0xffffffffu, s1, 1);
        s1 += __shfl_xor_sync(0xffffffffu, s1, 2);
        mloc1 = m0v; mloc2 = m1v; sloc1 = s0; sloc2 = s1;
    }

    // ---- wait V, then O = P V (band-skipped) ----
    CP_WAIT0();
    __syncthreads();

    float o[8][4];
    #pragma unroll
    for (int nt = 0; nt < 8; nt++)
        #pragma unroll
        for (int e = 0; e < 4; e++) o[nt][e] = 0.f;

    const uint32_t vb_row = (uint32_t)(half * 96 + (lane & 7) + ((lane & 8) ? 8 : 0));
    const uint32_t vb_coff = (uint32_t)((lane & 16) ? 8 : 0);

    #pragma unroll
    for (int kt = 0; kt < 6; kt++) {
        if (kt < pp_lo || kt > pp_hi) continue;
        uint32_t pa[4];
        {
            float* e0 = p[2*kt]; float* e1 = p[2*kt+1];
            pa[0] = pkh(e0[0], e0[1]);
            pa[1] = pkh(e0[2], e0[3]);
            pa[2] = pkh(e1[0], e1[1]);
            pa[3] = pkh(e1[2], e1[3]);
        }
        #pragma unroll
        for (int dp = 0; dp < 4; dp++) {
            uint32_t addr = smb + AV
                + ((vb_row + (uint32_t)(kt * 16)) * ARS + (uint32_t)(dp * 16) + vb_coff) * 2;
            uint32_t vv[4];
            LDM_X4_T(vv[0], vv[1], vv[2], vv[3], addr);
            #pragma unroll
            for (int sub = 0; sub < 2; sub++) {
                int nt = dp * 2 + sub;
                uint32_t bb2[2] = { vv[sub*2], vv[sub*2+1] };
                mma_f16(o[nt], pa, bb2);
            }
        }
    }

    // ---- combine halves (flash merge) and write ao ----
    if (half == 1) {
        #pragma unroll
        for (int nt = 0; nt < 8; nt++) {
            int col = nt * 8 + 2 * (lane & 3);
            *(float2*)&scratch[mt * 1024 + row_r * 64 + col] =
                make_float2(o[nt][0], o[nt][1]);
            *(float2*)&scratch[mt * 1024 + (row_r + 8) * 64 + col] =
                make_float2(o[nt][2], o[nt][3]);
        }
        if ((lane & 3) == 0) {
            redm[mt * 16 + row_r]     = mloc1;
            redm[mt * 16 + row_r + 8] = mloc2;
            reds[mt * 16 + row_r]     = sloc1;
            reds[mt * 16 + row_r + 8] = sloc2;
        }
    }
    __syncthreads();
    if (half == 0) {
        int r1g = q0 + mt * 16 + row_r;
        int r2g = r1g + 8;
        float m1o = redm[mt * 16 + row_r],     s1o = reds[mt * 16 + row_r];
        float m2o = redm[mt * 16 + row_r + 8], s2o = reds[mt * 16 + row_r + 8];
        float M1 = fmaxf(mloc1, m1o), M2 = fmaxf(mloc2, m2o);
        float wa1 = exp2f(mloc1 - M1), wb1 = exp2f(m1o - M1);
        float wa2 = exp2f(mloc2 - M2), wb2 = exp2f(m2o - M2);
        float inv1 = 1.0f / (sloc1 * wa1 + s1o * wb1);
        float inv2 = 1.0f / (sloc2 * wa2 + s2o * wb2);
        #pragma unroll
        for (int nt = 0; nt < 8; nt++) {
            int col = nt * 8 + 2 * (lane & 3);
            float2 s1v = *(float2*)&scratch[mt * 1024 + row_r * 64 + col];
            float2 s2v = *(float2*)&scratch[mt * 1024 + (row_r + 8) * 64 + col];
            float w10 = (o[nt][0] * wa1 + s1v.x * wb1) * inv1;
            float w11 = (o[nt][1] * wa1 + s1v.y * wb1) * inv1;
            float w20 = (o[nt][2] * wa2 + s2v.x * wb2) * inv2;
            float w21 = (o[nt][3] * wa2 + s2v.y * wb2) * inv2;
            *(uint32_t*)(ao + ((size_t)bb * T + r1g) * DIM + h * 64 + col) = pkh(w10, w11);
            *(uint32_t*)(ao + ((size_t)bb * T + r2g) * DIM + h * 64 + col) = pkh(w20, w21);
        }
    }
}

// ---------------------------------------------------------------------------
extern "C" void kernel_launch(void* const* d_in, const int* in_sizes, int n_in,
                              void* d_out, int out_size)
{
    const float* x    = (const float*)d_in[0];
    const float* rope = (const float*)d_in[2];
    const float* Wq   = (const float*)d_in[3];
    const float* Wk   = (const float*)d_in[4];
    const float* Wv   = (const float*)d_in[5];
    const float* Wo   = (const float*)d_in[6];
    float* out = (float*)d_out;

    __half *xh, *whi, *qh, *kh, *vh, *aoh;
    cudaGetSymbolAddress((void**)&xh,  g_xh);
    cudaGetSymbolAddress((void**)&whi, g_whi);
    cudaGetSymbolAddress((void**)&qh,  g_qh);
    cudaGetSymbolAddress((void**)&kh,  g_kh);
    cudaGetSymbolAddress((void**)&vh,  g_vh);
    cudaGetSymbolAddress((void**)&aoh, g_aoh);

    cudaFuncSetAttribute(gemm_hmma, cudaFuncAttributeMaxDynamicSharedMemorySize, GEMM_SMEM);
    cudaFuncSetAttribute(attn_hmma, cudaFuncAttributeMaxDynamicSharedMemorySize, ATT_SMEM);

    const int xn4 = XSZ / 4;
    const int wn4tot = 4 * WSZ / 4;

    tohalf<<<xn4 / 256, 256>>>(x, xh, xn4);
    split_w4<<<wn4tot / 256, 256>>>(Wq, Wk, Wv, Wo, whi);

    // fused QKV (N = 3072, 1-pass)
    gemm_hmma<<<dim3(24, 32), 256, GEMM_SMEM>>>(xh, whi, nullptr, qh, kh, vh, 1);

    int nrope = B * H * T * 4;
    rope_prep<<<(nrope + 255) / 256, 256>>>(qh, kh, rope);

    attn_hmma<<<dim3(T / 64, H, B), 256, ATT_SMEM>>>(qh, kh, vh, aoh);

    // O projection (1-pass)
    gemm_hmma<<<dim3(8, 32), 256, GEMM_SMEM>>>(aoh, whi + 3*(size_t)WSZ,
                                               out, nullptr, nullptr, nullptr, 0);
}

// round 17
// speedup vs baseline: 3.6167x; 1.0004x over previous
#include <cuda_runtime.h>
#include <cuda_fp16.h>
#include <math.h>
#include <stdint.h>

#define B 2
#define T 2048
#define H 16
#define DH 64
#define DIM 1024
#define M_TOTAL (B*T)      // 4096
#define SZH (B*H*T*DH)     // 4194304
#define XSZ (M_TOTAL*DIM)  // 4194304
#define WSZ (DIM*DIM)      // 1048576
#define ATT_SCALE_L2 0.18033688011112042f   // 0.125 * log2(e)

// ---------------- scratch (device globals; allocation-free) ----------------
__device__ __half g_xh [XSZ];
__device__ __half g_whi[4*WSZ];
__device__ __half g_qh [SZH];
__device__ __half g_kh [SZH];
__device__ __half g_vh [SZH];
__device__ __half g_aoh[XSZ];

// ---------------- helpers ----------------
__device__ __forceinline__ uint32_t smem_u32(const void* p) {
    uint32_t a;
    asm("{ .reg .u64 t; cvta.to.shared.u64 t, %1; cvt.u32.u64 %0, t; }"
        : "=r"(a) : "l"(p));
    return a;
}

#define CP_ASYNC16(dst_u32, src_ptr) \
    asm volatile("cp.async.cg.shared.global [%0], [%1], 16;" :: "r"(dst_u32), "l"(src_ptr))
#define CP_COMMIT()  asm volatile("cp.async.commit_group;" ::: "memory")
#define CP_WAIT0()   asm volatile("cp.async.wait_group 0;" ::: "memory")
#define CP_WAIT1()   asm volatile("cp.async.wait_group 1;" ::: "memory")

#define LDM_X4(r0,r1,r2,r3, addr) \
    asm volatile("ldmatrix.sync.aligned.m8n8.x4.shared.b16 {%0,%1,%2,%3}, [%4];" \
                 : "=r"(r0), "=r"(r1), "=r"(r2), "=r"(r3) : "r"(addr))
#define LDM_X4_T(r0,r1,r2,r3, addr) \
    asm volatile("ldmatrix.sync.aligned.m8n8.x4.trans.shared.b16 {%0,%1,%2,%3}, [%4];" \
                 : "=r"(r0), "=r"(r1), "=r"(r2), "=r"(r3) : "r"(addr))

__device__ __forceinline__ void mma_f16(float* c, const uint32_t* a, const uint32_t* b) {
    asm volatile(
        "mma.sync.aligned.m16n8k16.row.col.f32.f16.f16.f32 "
        "{%0,%1,%2,%3}, {%4,%5,%6,%7}, {%8,%9}, {%0,%1,%2,%3};"
        : "+f"(c[0]), "+f"(c[1]), "+f"(c[2]), "+f"(c[3])
        : "r"(a[0]), "r"(a[1]), "r"(a[2]), "r"(a[3]), "r"(b[0]), "r"(b[1]));
}

__device__ __forceinline__ uint32_t pkh(float a, float b) {
    __half2 t = __floats2half2_rn(a, b);
    return *(uint32_t*)&t;
}

// ---------------------------------------------------------------------------
// Unified fp32 -> fp16 conversion: x + 4 weight matrices, one launch.
// i in [0, 2^20): x ; else 4 segments of 2^18 float4 for W0..W3.
// ---------------------------------------------------------------------------
__global__ void prep_half(const float* __restrict__ x,
                          const float* __restrict__ W0, const float* __restrict__ W1,
                          const float* __restrict__ W2, const float* __restrict__ W3,
                          __half* __restrict__ xh, __half* __restrict__ whi)
{
    int i = blockIdx.x * blockDim.x + threadIdx.x;   // 0 .. 2*2^20-1
    const float* src;
    __half* dst;
    size_t j;
    if (i < (1 << 20)) {
        src = x; dst = xh; j = (size_t)i;
    } else {
        int r = i - (1 << 20);
        int which = r >> 18;
        j = (size_t)(r & 0x3FFFF);
        src = (which == 0) ? W0 : (which == 1) ? W1 : (which == 2) ? W2 : W3;
        dst = whi + (size_t)which * WSZ;
    }
    float4 v = ((const float4*)src)[j];
    uint2 u;
    u.x = pkh(v.x, v.y);
    u.y = pkh(v.z, v.w);
    *(uint2*)(dst + 4 * j) = u;
}

// ---------------------------------------------------------------------------
// RoPE prep (IN-PLACE, Q/K split across threads for 2x parallelism).
// idx < N: Q rows (folds scale*log2e); idx >= N: K rows.
// Each thread owns 8 consecutive (d, d+32) pairs of one (b,h,t) row.
// ---------------------------------------------------------------------------
__global__ void rope_prep(__half* __restrict__ q, __half* __restrict__ k,
                          const float* __restrict__ rope)
{
    const int N = B * H * T * 4;
    int idx = blockIdx.x * blockDim.x + threadIdx.x;   // 2*N
    if (idx >= 2 * N) return;
    bool isQ = idx < N;
    int li = isQ ? idx : idx - N;
    int d8   = (li & 3) * 8;
    int rest = li >> 2;
    int t    = rest & (T - 1);
    int bh   = rest >> 11;
    int bidx = bh >> 4;

    const float* pr = rope + ((size_t)bidx * T + t) * DH + d8;
    float p1[8], p2[8];
    *(float4*)(p1)     = *(const float4*)(pr);
    *(float4*)(p1 + 4) = *(const float4*)(pr + 4);
    *(float4*)(p2)     = *(const float4*)(pr + 32);
    *(float4*)(p2 + 4) = *(const float4*)(pr + 36);

    float c1[8], s1[8], c2[8], s2[8];
    #pragma unroll
    for (int e = 0; e < 8; e++) {
        __sincosf(p1[e], &s1[e], &c1[e]);
        __sincosf(p2[e], &s2[e], &c2[e]);
    }

    __half* buf = isQ ? q : k;
    const float sc = isQ ? ATT_SCALE_L2 : 1.0f;
    size_t base = (size_t)rest * DH + d8;

    uint4 ua = *(uint4*)(buf + base);
    uint4 ub = *(uint4*)(buf + base + 32);
    __half* ha = (__half*)&ua;
    __half* hb = (__half*)&ub;
    uint4 oa, ob;
    __half* oa_h = (__half*)&oa;
    __half* ob_h = (__half*)&ob;
    #pragma unroll
    for (int e = 0; e < 8; e++) {
        float x1 = __half2float(ha[e]);
        float x2 = __half2float(hb[e]);
        oa_h[e] = __float2half_rn((x1 * c1[e] - x2 * s1[e]) * sc);
        ob_h[e] = __float2half_rn((x2 * c2[e] + x1 * s2[e]) * sc);
    }
    *(uint4*)(buf + base)      = oa;
    *(uint4*)(buf + base + 32) = ob;
}

// ---------------------------------------------------------------------------
// Tensor-core GEMM, BK=64, single-pass fp16: C[m,n] = sum_k A[m,k]*W[n,k]
// mode 0: Cf fp32 row-major (O proj)
// mode 1: QKV fused (grid.x=24): which=n0>>10 -> Cq/Ck/Cv fp16 scatter
// ---------------------------------------------------------------------------
#define BK64 64
#define GRS 72
#define GTILE (128*GRS*2)              // 18432 bytes
#define GEMM_SMEM (2*2*GTILE)          // 73728

__global__ __launch_bounds__(256) void gemm_hmma(
    const __half* __restrict__ A,
    const __half* __restrict__ Wh,
    float* __restrict__ Cf,
    __half* __restrict__ Cq, __half* __restrict__ Ck, __half* __restrict__ Cv,
    int mode)
{
    extern __shared__ __align__(16) char sm[];
    const uint32_t smb = smem_u32(sm);

    const int tid  = threadIdx.x;
    const int m0   = blockIdx.y * 128;
    const int n0   = blockIdx.x * 128;
    const int wid  = tid >> 5;
    const int lane = tid & 31;
    const int g    = lane >> 2;
    const int t2   = (lane & 3) * 2;
    const int wm   = (wid & 1) * 64;
    const int wn   = (wid >> 1) * 32;

    float acc[4][4][4];
    #pragma unroll
    for (int mt = 0; mt < 4; mt++)
        #pragma unroll
        for (int nt = 0; nt < 4; nt++)
            #pragma unroll
            for (int e = 0; e < 4; e++) acc[mt][nt][e] = 0.f;

    auto load_chunk = [&](int c, int buf) {
        const int k0 = c * BK64;
        const uint32_t bb = smb + (uint32_t)buf * (2u * GTILE);
        #pragma unroll
        for (int i = 0; i < 8; i++) {
            int idx = tid + i * 256;      // 0..2047
            int arr = idx >> 10;          // 0..1
            int rem = idx & 1023;
            int r   = rem >> 3;
            int c8  = (rem & 7) * 8;
            const __half* src = arr ? Wh : A;
            int rowbase = (arr ? n0 : m0) + r;
            uint32_t dst = bb + (uint32_t)arr * GTILE + (uint32_t)(r * GRS + c8) * 2;
            CP_ASYNC16(dst, src + (size_t)rowbase * DIM + k0 + c8);
        }
    };

    const uint32_t a_off = (uint32_t)((wm + (lane & 15)) * GRS + ((lane & 16) ? 8 : 0));
    const uint32_t b_off = (uint32_t)((wn + (lane & 7) + ((lane & 16) ? 8 : 0)) * GRS
                                      + ((lane & 8) ? 8 : 0));

    const int NC = DIM / BK64;   // 16
    load_chunk(0, 0);
    CP_COMMIT();

    for (int c = 0; c < NC; c++) {
        if (c + 1 < NC) {
            load_chunk(c + 1, (c + 1) & 1);
            CP_COMMIT();
            CP_WAIT1();
        } else {
            CP_WAIT0();
        }
        __syncthreads();

        const uint32_t base = smb + (uint32_t)(c & 1) * (2u * GTILE);

        #pragma unroll
        for (int ks = 0; ks < 4; ks++) {
            const uint32_t kc = (uint32_t)(ks * 16);
            uint32_t ar[4][4], wh[2][4];
            #pragma unroll
            for (int mt = 0; mt < 4; mt++) {
                uint32_t addr = base + (a_off + (uint32_t)(mt * 16) * GRS + kc) * 2;
                LDM_X4(ar[mt][0], ar[mt][1], ar[mt][2], ar[mt][3], addr);
            }
            #pragma unroll
            for (int p = 0; p < 2; p++) {
                uint32_t addr = base + GTILE + (b_off + (uint32_t)(p * 16) * GRS + kc) * 2;
                LDM_X4(wh[p][0], wh[p][1], wh[p][2], wh[p][3], addr);
            }
            #pragma unroll
            for (int mt = 0; mt < 4; mt++)
                #pragma unroll
                for (int nt = 0; nt < 4; nt++) {
                    uint32_t bh[2] = { wh[nt>>1][(nt&1)*2], wh[nt>>1][(nt&1)*2+1] };
                    mma_f16(acc[mt][nt], ar[mt], bh);
                }
        }
        __syncthreads();
    }

    // ---- epilogue ----
    if (mode == 0) {
        #pragma unroll
        for (int mt = 0; mt < 4; mt++) {
            int row0 = m0 + wm + mt * 16 + g;
            #pragma unroll
            for (int nt = 0; nt < 4; nt++) {
                int col = n0 + wn + nt * 8 + t2;
                *(float2*)(Cf + (size_t)row0 * DIM + col) =
                    make_float2(acc[mt][nt][0], acc[mt][nt][1]);
                *(float2*)(Cf + (size_t)(row0 + 8) * DIM + col) =
                    make_float2(acc[mt][nt][2], acc[mt][nt][3]);
            }
        }
    } else {
        int which = n0 >> 10;
        __half* C = (which == 0) ? Cq : (which == 1) ? Ck : Cv;
        int n0w = n0 & 1023;
        #pragma unroll
        for (int mt = 0; mt < 4; mt++) {
            int row0 = m0 + wm + mt * 16 + g;
            int bb0 = row0 >> 11, t0 = row0 & (T - 1);
            int bb1 = (row0 + 8) >> 11, t1 = (row0 + 8) & (T - 1);
            #pragma unroll
            for (int nt = 0; nt < 4; nt++) {
                int col = n0w + wn + nt * 8 + t2;
                int h = col >> 6, d = col & 63;
                size_t i0 = (((size_t)bb0 * H + h) * T + t0) * DH + d;
                size_t i1 = (((size_t)bb1 * H + h) * T + t1) * DH + d;
                *(uint32_t*)(C + i0) = pkh(acc[mt][nt][0], acc[mt][nt][1]);
                *(uint32_t*)(C + i1) = pkh(acc[mt][nt][2], acc[mt][nt][3]);
            }
        }
    }
}

// ---------------------------------------------------------------------------
// Tensor-core sliding-window attention, flash-style half-merge + band skip.
// Block = (64 queries, h, b); keys [q0-128, q0+63] -> 192; 2 key-halves of 96.
// Warp (mt, half) needs only key-chunks: half0 pp in [mt,5], half1 pp in [0,2+mt].
// ---------------------------------------------------------------------------
#define ARS 72
#define AQ  0
#define AK  (64*ARS*2)               // 9216
#define AV  (AK + 192*ARS*2)         // 36864
#define ARED (AV + 192*ARS*2)        // 64512
#define ATT_SMEM (ARED + 1024)       // 65536

__global__ __launch_bounds__(256, 2) void attn_hmma(
    const __half* __restrict__ qh, const __half* __restrict__ kh,
    const __half* __restrict__ vh,
    __half* __restrict__ ao)
{
    extern __shared__ __align__(16) char sm[];
    const uint32_t smb = smem_u32(sm);
    float* redm = (float*)(sm + ARED);
    float* reds = (float*)(sm + ARED + 256);
    float* scratch = (float*)sm;                // 16KB, overlaps AQ+AK (dead post-S)

    const int q0 = blockIdx.x * 64;
    const int h  = blockIdx.y;
    const int bb = blockIdx.z;
    const int tid = threadIdx.x;
    const int wid = tid >> 5;
    const int lane = tid & 31;
    const size_t headbase = ((size_t)bb * H + h) * T * DH;
    const int k0 = q0 - 128;

    // ---- group A: Q + K ----
    for (int i = tid; i < 512; i += 256) {
        int r = i >> 3, s = i & 7;
        CP_ASYNC16(smb + AQ + (uint32_t)(r * ARS + s * 8) * 2,
                   qh + headbase + (size_t)(q0 + r) * DH + s * 8);
    }
    for (int i = tid; i < 1536; i += 256) {
        int r = i >> 3, s = i & 7;
        int kg = k0 + r;
        int kc = kg < 0 ? 0 : (kg >= T ? T - 1 : kg);
        CP_ASYNC16(smb + AK + (uint32_t)(r * ARS + s * 8) * 2,
                   kh + headbase + (size_t)kc * DH + s * 8);
    }
    CP_COMMIT();
    // ---- group B: V (overlaps S) ----
    for (int i = tid; i < 1536; i += 256) {
        int r = i >> 3, s = i & 7;
        int kg = k0 + r;
        int kc = kg < 0 ? 0 : (kg >= T ? T - 1 : kg);
        CP_ASYNC16(smb + AV + (uint32_t)(r * ARS + s * 8) * 2,
                   vh + headbase + (size_t)kc * DH + s * 8);
    }
    CP_COMMIT();
    CP_WAIT1();
    __syncthreads();

    const int mt   = wid & 3;
    const int half = wid >> 2;
    const int row_r = lane >> 2;

    const int pp_lo = half ? 0 : mt;
    const int pp_hi = half ? (2 + mt) : 5;

    // ---- S = Q K^T (band-skipped) ----
    float p[12][4];
    #pragma unroll
    for (int nt = 0; nt < 12; nt++)
        #pragma unroll
        for (int e = 0; e < 4; e++) p[nt][e] = 0.f;

    const uint32_t qa_off = (uint32_t)((mt * 16 + (lane & 15)) * ARS
                                       + ((lane & 16) ? 8 : 0)) * 2;
    const uint32_t kb_row = (uint32_t)(half * 96 + (lane & 7) + ((lane & 16) ? 8 : 0));
    const uint32_t kb_coff = (uint32_t)((lane & 8) ? 8 : 0);

    #pragma unroll
    for (int kt = 0; kt < 4; kt++) {
        const uint32_t kc = (uint32_t)(kt * 16);
        uint32_t aq[4];
        LDM_X4(aq[0], aq[1], aq[2], aq[3], smb + AQ + qa_off + kc * 2);
        #pragma unroll
        for (int pp = 0; pp < 6; pp++) {
            if (pp < pp_lo || pp > pp_hi) continue;
            uint32_t addr = smb + AK
                + ((kb_row + (uint32_t)(pp * 16)) * ARS + kc + kb_coff) * 2;
            uint32_t bh[4];
            LDM_X4(bh[0], bh[1], bh[2], bh[3], addr);
            #pragma unroll
            for (int sub = 0; sub < 2; sub++) {
                int nt = pp * 2 + sub;
                uint32_t bbh[2] = { bh[sub*2], bh[sub*2+1] };
                mma_f16(p[nt], aq, bbh);
            }
        }
    }

    // ---- mask ----
    {
        int qg1 = q0 + mt * 16 + row_r;
        int qg2 = qg1 + 8;
        #pragma unroll
        for (int nt = 0; nt < 12; nt++) {
            int cb = k0 + half * 96 + nt * 8 + 2 * (lane & 3);
            #pragma unroll
            for (int e = 0; e < 4; e++) {
                int kg = cb + (e & 1);
                int qg = (e & 2) ? qg2 : qg1;
                bool valid = (kg >= 0) && (kg <= qg) && (kg >= qg - 128);
                if (!valid) p[nt][e] = -1e30f;
            }
        }
    }

    // ---- local softmax (in-warp only) ----
    float mloc1, mloc2, sloc1, sloc2;
    {
        float m0v = -1e30f, m1v = -1e30f;
        #pragma unroll
        for (int nt = 0; nt < 12; nt++) {
            m0v = fmaxf(m0v, fmaxf(p[nt][0], p[nt][1]));
            m1v = fmaxf(m1v, fmaxf(p[nt][2], p[nt][3]));
        }
        m0v = fmaxf(m0v, __shfl_xor_sync(0xffffffffu, m0v, 1));
        m0v = fmaxf(m0v, __shfl_xor_sync(0xffffffffu, m0v, 2));
        m1v = fmaxf(m1v, __shfl_xor_sync(0xffffffffu, m1v, 1));
        m1v = fmaxf(m1v, __shfl_xor_sync(0xffffffffu, m1v, 2));

        float s0 = 0.f, s1 = 0.f;
        #pragma unroll
        for (int nt = 0; nt < 12; nt++) {
            p[nt][0] = exp2f(p[nt][0] - m0v); s0 += p[nt][0];
            p[nt][1] = exp2f(p[nt][1] - m0v); s0 += p[nt][1];
            p[nt][2] = exp2f(p[nt][2] - m1v); s1 += p[nt][2];
            p[nt][3] = exp2f(p[nt][3] - m1v); s1 += p[nt][3];
        }
        s0 += __shfl_xor_sync(0xffffffffu, s0, 1);
        s0 += __shfl_xor_sync(0xffffffffu, s0, 2);
        s1 += __shfl_xor_sync(0xffffffffu, s1, 1);
        s1 += __shfl_xor_sync(0xffffffffu, s1, 2);
        mloc1 = m0v; mloc2 = m1v; sloc1 = s0; sloc2 = s1;
    }

    // ---- wait V, then O = P V (band-skipped) ----
    CP_WAIT0();
    __syncthreads();

    float o[8][4];
    #pragma unroll
    for (int nt = 0; nt < 8; nt++)
        #pragma unroll
        for (int e = 0; e < 4; e++) o[nt][e] = 0.f;

    const uint32_t vb_row = (uint32_t)(half * 96 + (lane & 7) + ((lane & 8) ? 8 : 0));
    const uint32_t vb_coff = (uint32_t)((lane & 16) ? 8 : 0);

    #pragma unroll
    for (int kt = 0; kt < 6; kt++) {
        if (kt < pp_lo || kt > pp_hi) continue;
        uint32_t pa[4];
        {
            float* e0 = p[2*kt]; float* e1 = p[2*kt+1];
            pa[0] = pkh(e0[0], e0[1]);
            pa[1] = pkh(e0[2], e0[3]);
            pa[2] = pkh(e1[0], e1[1]);
            pa[3] = pkh(e1[2], e1[3]);
        }
        #pragma unroll
        for (int dp = 0; dp < 4; dp++) {
            uint32_t addr = smb + AV
                + ((vb_row + (uint32_t)(kt * 16)) * ARS + (uint32_t)(dp * 16) + vb_coff) * 2;
            uint32_t vv[4];
            LDM_X4_T(vv[0], vv[1], vv[2], vv[3], addr);
            #pragma unroll
            for (int sub = 0; sub < 2; sub++) {
                int nt = dp * 2 + sub;
                uint32_t bb2[2] = { vv[sub*2], vv[sub*2+1] };
                mma_f16(o[nt], pa, bb2);
            }
        }
    }

    // ---- combine halves (flash merge) and write ao ----
    if (half == 1) {
        #pragma unroll
        for (int nt = 0; nt < 8; nt++) {
            int col = nt * 8 + 2 * (lane & 3);
            *(float2*)&scratch[mt * 1024 + row_r * 64 + col] =
                make_float2(o[nt][0], o[nt][1]);
            *(float2*)&scratch[mt * 1024 + (row_r + 8) * 64 + col] =
                make_float2(o[nt][2], o[nt][3]);
        }
        if ((lane & 3) == 0) {
            redm[mt * 16 + row_r]     = mloc1;
            redm[mt * 16 + row_r + 8] = mloc2;
            reds[mt * 16 + row_r]     = sloc1;
            reds[mt * 16 + row_r + 8] = sloc2;
        }
    }
    __syncthreads();
    if (half == 0) {
        int r1g = q0 + mt * 16 + row_r;
        int r2g = r1g + 8;
        float m1o = redm[mt * 16 + row_r],     s1o = reds[mt * 16 + row_r];
        float m2o = redm[mt * 16 + row_r + 8], s2o = reds[mt * 16 + row_r + 8];
        float M1 = fmaxf(mloc1, m1o), M2 = fmaxf(mloc2, m2o);
        float wa1 = exp2f(mloc1 - M1), wb1 = exp2f(m1o - M1);
        float wa2 = exp2f(mloc2 - M2), wb2 = exp2f(m2o - M2);
        float inv1 = 1.0f / (sloc1 * wa1 + s1o * wb1);
        float inv2 = 1.0f / (sloc2 * wa2 + s2o * wb2);
        #pragma unroll
        for (int nt = 0; nt < 8; nt++) {
            int col = nt * 8 + 2 * (lane & 3);
            float2 s1v = *(float2*)&scratch[mt * 1024 + row_r * 64 + col];
            float2 s2v = *(float2*)&scratch[mt * 1024 + (row_r + 8) * 64 + col];
            float w10 = (o[nt][0] * wa1 + s1v.x * wb1) * inv1;
            float w11 = (o[nt][1] * wa1 + s1v.y * wb1) * inv1;
            float w20 = (o[nt][2] * wa2 + s2v.x * wb2) * inv2;
            float w21 = (o[nt][3] * wa2 + s2v.y * wb2) * inv2;
            *(uint32_t*)(ao + ((size_t)bb * T + r1g) * DIM + h * 64 + col) = pkh(w10, w11);
            *(uint32_t*)(ao + ((size_t)bb * T + r2g) * DIM + h * 64 + col) = pkh(w20, w21);
        }
    }
}

// ---------------------------------------------------------------------------
extern "C" void kernel_launch(void* const* d_in, const int* in_sizes, int n_in,
                              void* d_out, int out_size)
{
    const float* x    = (const float*)d_in[0];
    const float* rope = (const float*)d_in[2];
    const float* Wq   = (const float*)d_in[3];
    const float* Wk   = (const float*)d_in[4];
    const float* Wv   = (const float*)d_in[5];
    const float* Wo   = (const float*)d_in[6];
    float* out = (float*)d_out;

    __half *xh, *whi, *qh, *kh, *vh, *aoh;
    cudaGetSymbolAddress((void**)&xh,  g_xh);
    cudaGetSymbolAddress((void**)&whi, g_whi);
    cudaGetSymbolAddress((void**)&qh,  g_qh);
    cudaGetSymbolAddress((void**)&kh,  g_kh);
    cudaGetSymbolAddress((void**)&vh,  g_vh);
    cudaGetSymbolAddress((void**)&aoh, g_aoh);

    cudaFuncSetAttribute(gemm_hmma, cudaFuncAttributeMaxDynamicSharedMemorySize, GEMM_SMEM);
    cudaFuncSetAttribute(attn_hmma, cudaFuncAttributeMaxDynamicSharedMemorySize, ATT_SMEM);

    // one unified conversion launch: x + Wq/Wk/Wv/Wo  (2*2^20 float4 tasks)
    prep_half<<<(2 << 20) / 256, 256>>>(x, Wq, Wk, Wv, Wo, xh, whi);

    // fused QKV (N = 3072, 1-pass)
    gemm_hmma<<<dim3(24, 32), 256, GEMM_SMEM>>>(xh, whi, nullptr, qh, kh, vh, 1);

    // RoPE in-place, Q/K split across threads
    int nrope = 2 * B * H * T * 4;
    rope_prep<<<(nrope + 255) / 256, 256>>>(qh, kh, rope);

    attn_hmma<<<dim3(T / 64, H, B), 256, ATT_SMEM>>>(qh, kh, vh, aoh);

    // O projection (1-pass)
    gemm_hmma<<<dim3(8, 32), 256, GEMM_SMEM>>>(aoh, whi + 3*(size_t)WSZ,
                                               out, nullptr, nullptr, nullptr, 0);
}